// round 14
// baseline (speedup 1.0000x reference)
#include <cuda_runtime.h>
#include <cuda_fp16.h>
#include <math.h>
#include <cstdint>

// ---------------------------------------------------------------------------
// Transformer block. All GEMMs + attention via mma.sync fp16 (fp32 accum),
// ldmatrix fragment loads. GEMM: 128x128, BK=32, 3-stage cp.async pipeline.
// M=4096, D=1024, H=16, hd=64, FF=4096.
// ---------------------------------------------------------------------------

#define MTOK 4096
#define DDIM 1024
#define QKVD 3072
#define FFDIM 4096
#define NHEAD 16
#define HDIM 64
#define SEQ 2048
#define BATCH 2

// scratch layout (units: floats)
#define OFF_QKVH  ((size_t)0)
#define OFF_X1    (OFF_QKVH + (size_t)MTOK*QKVD/2)
#define OFF_X2    (OFF_X1   + (size_t)MTOK*DDIM)
#define OFF_X3    (OFF_X2   + (size_t)MTOK*DDIM)
#define OFF_ATTH  (OFF_X3   + (size_t)MTOK*DDIM)
#define OFF_X2H   (OFF_ATTH + (size_t)MTOK*DDIM/2)
#define OFF_HH    (OFF_X2H  + (size_t)MTOK*DDIM/2)
#define OFF_XH    (OFF_HH   + (size_t)MTOK*FFDIM/2)
#define OFF_WQKVT (OFF_XH   + (size_t)MTOK*DDIM/2)
#define OFF_WOT   (OFF_WQKVT+ (size_t)QKVD*DDIM/2)
#define OFF_W1T   (OFF_WOT  + (size_t)DDIM*DDIM/2)
#define OFF_W2T   (OFF_W1T  + (size_t)DDIM*FFDIM/2)
#define OFF_BQKV  (OFF_W2T  + (size_t)FFDIM*DDIM/2)
#define SCRATCH_FLOATS (OFF_BQKV + (size_t)QKVD)

__device__ float g_scratch[SCRATCH_FLOATS];

// ---------------- PTX helpers ----------------
__device__ __forceinline__ void cp_async16(uint32_t dst, const void* src) {
    asm volatile("cp.async.cg.shared.global [%0], [%1], 16;"
                 :: "r"(dst), "l"(src) : "memory");
}
__device__ __forceinline__ void cp_commit() {
    asm volatile("cp.async.commit_group;" ::: "memory");
}
__device__ __forceinline__ void cp_wait0() {
    asm volatile("cp.async.wait_group 0;" ::: "memory");
}
__device__ __forceinline__ void cp_wait1() {
    asm volatile("cp.async.wait_group 1;" ::: "memory");
}
__device__ __forceinline__ void cp_wait2() {
    asm volatile("cp.async.wait_group 2;" ::: "memory");
}
__device__ __forceinline__ uint32_t smem_u32(const void* p) {
    uint32_t a;
    asm("{ .reg .u64 t; cvta.to.shared.u64 t, %1; cvt.u32.u64 %0, t; }"
        : "=r"(a) : "l"(p));
    return a;
}
__device__ __forceinline__ void mma_f16(float* c, const uint32_t* a,
                                        const uint32_t* b) {
    asm volatile(
        "mma.sync.aligned.m16n8k16.row.col.f32.f16.f16.f32 "
        "{%0,%1,%2,%3}, {%4,%5,%6,%7}, {%8,%9}, {%0,%1,%2,%3};"
        : "+f"(c[0]), "+f"(c[1]), "+f"(c[2]), "+f"(c[3])
        : "r"(a[0]), "r"(a[1]), "r"(a[2]), "r"(a[3]), "r"(b[0]), "r"(b[1]));
}
__device__ __forceinline__ void ldmx4(uint32_t* r, uint32_t addr) {
    asm volatile(
        "ldmatrix.sync.aligned.m8n8.x4.shared.b16 {%0,%1,%2,%3}, [%4];"
        : "=r"(r[0]), "=r"(r[1]), "=r"(r[2]), "=r"(r[3]) : "r"(addr));
}
__device__ __forceinline__ void ldmx4_trans(uint32_t* r, uint32_t addr) {
    asm volatile(
        "ldmatrix.sync.aligned.m8n8.x4.trans.shared.b16 {%0,%1,%2,%3}, [%4];"
        : "=r"(r[0]), "=r"(r[1]), "=r"(r[2]), "=r"(r[3]) : "r"(addr));
}

// Fast exp on the FMA pipe (no MUFU).
__device__ __forceinline__ float fexp(float x) {
    float t = x * 1.4426950408889634f;
    t = fmaxf(t, -126.0f);
    const float fn = rintf(t);
    const float f = t - fn;
    float p = 1.33336500e-3f;
    p = fmaf(p, f, 9.61823766e-3f);
    p = fmaf(p, f, 5.55041087e-2f);
    p = fmaf(p, f, 2.40226507e-1f);
    p = fmaf(p, f, 6.93147182e-1f);
    p = fmaf(p, f, 1.0f);
    const int n = (int)fn;
    return p * __int_as_float((n + 127) << 23);
}

// ---------------------------------------------------------------------------
// fp16 GEMM: C[M,N] = A[M,K] @ Bt[N,K]^T + bias (+ epilogue)
// CTA 128x128, BK=32 halfs, 256 threads, 3-stage cp.async pipeline,
// ldmatrix.x4 fragment loads (144 B row stride, conflict-free).
// ---------------------------------------------------------------------------
#define BM 128
#define BN 128
#define NSTAGE 3
#define ATILE_B (128 * 144)
#define BTILE_B (128 * 144)
#define GT_SMEM (NSTAGE * (ATILE_B + BTILE_B))   // 110592

template <int EPI, int HOUT>
__global__ __launch_bounds__(256, 2)
void gemm_h(const __half* __restrict__ A, const __half* __restrict__ Bt,
            const float* __restrict__ bias, const float* __restrict__ res,
            void* __restrict__ Cout, int M, int N, int K)
{
    extern __shared__ __half smh[];
    const uint32_t As_u = smem_u32(smh);
    const uint32_t Bs_u = As_u + NSTAGE * ATILE_B;

    const int tid  = threadIdx.x;
    const int warp = tid >> 5;
    const int lane = tid & 31;
    const int g    = lane >> 2;
    const int t4   = lane & 3;
    const int wm   = warp >> 2;     // 0..1, 64 rows
    const int wn   = warp & 3;      // 0..3, 32 cols

    const int m0 = blockIdx.y * BM;
    const int n0 = blockIdx.x * BN;

    // loaders: 128 rows x 4 chunks of 16B each for A and B; 256 thr x 2 each
    const int lrow = tid >> 1;
    const int l16  = (tid & 1) * 2;
    const __half* Ag = A + (size_t)(m0 + lrow) * K + l16 * 8;
    const __half* Bg = Bt + (size_t)(n0 + lrow) * K + l16 * 8;
    const uint32_t Asm = As_u + (uint32_t)(lrow * 144 + l16 * 16);
    const uint32_t Bsm = Bs_u + (uint32_t)(lrow * 144 + l16 * 16);

    // ldmatrix per-lane offsets
    const uint32_t aLane = (uint32_t)((wm * 64 + (lane & 15)) * 144 +
                                      (lane >> 4) * 16);
    const uint32_t bLane = (uint32_t)((wn * 32 + (lane >> 4) * 8 + (lane & 7)) * 144 +
                                      ((lane >> 3) & 1) * 16);

    float acc[4][4][4];
#pragma unroll
    for (int mi = 0; mi < 4; mi++)
#pragma unroll
        for (int ni = 0; ni < 4; ni++)
#pragma unroll
            for (int r = 0; r < 4; r++) acc[mi][ni][r] = 0.0f;

    const int T = K >> 5;   // always >= 32 here

    // prologue: tiles 0 and 1 into stages 0 and 1
#pragma unroll
    for (int s = 0; s < 2; s++) {
        const uint32_t ao = (uint32_t)(s * ATILE_B);
        const uint32_t bo = (uint32_t)(s * BTILE_B);
        const size_t ko = (size_t)s * 32;
        cp_async16(Asm + ao, Ag + ko);
        cp_async16(Asm + ao + 16, Ag + ko + 8);
        cp_async16(Bsm + bo, Bg + ko);
        cp_async16(Bsm + bo + 16, Bg + ko + 8);
        cp_commit();
    }

    int cs = 0;   // compute stage
    for (int tb = 0; tb < T; tb++) {
        if (tb + 2 < T) {
            int ps = cs + 2; if (ps >= NSTAGE) ps -= NSTAGE;
            const uint32_t ao = (uint32_t)(ps * ATILE_B);
            const uint32_t bo = (uint32_t)(ps * BTILE_B);
            const size_t ko = (size_t)(tb + 2) * 32;
            cp_async16(Asm + ao, Ag + ko);
            cp_async16(Asm + ao + 16, Ag + ko + 8);
            cp_async16(Bsm + bo, Bg + ko);
            cp_async16(Bsm + bo + 16, Bg + ko + 8);
            cp_commit();
            cp_wait2();
        } else if (tb + 1 < T) {
            cp_wait1();
        } else {
            cp_wait0();
        }
        __syncthreads();

        const uint32_t aBase = As_u + (uint32_t)(cs * ATILE_B) + aLane;
        const uint32_t bBase = Bs_u + (uint32_t)(cs * BTILE_B) + bLane;
#pragma unroll
        for (int kk = 0; kk < 2; kk++) {
            uint32_t bf4[2][4];
            uint32_t af[2][4];
            ldmx4(bf4[0], bBase + kk * 32);
            ldmx4(bf4[1], bBase + 16 * 144 + kk * 32);
            ldmx4(af[0], aBase + kk * 32);
#pragma unroll
            for (int mi = 0; mi < 4; mi++) {
                if (mi < 3)
                    ldmx4(af[(mi + 1) & 1], aBase + (mi + 1) * (16 * 144) + kk * 32);
                const uint32_t* am = af[mi & 1];
#pragma unroll
                for (int ni = 0; ni < 4; ni++)
                    mma_f16(acc[mi][ni], am, bf4[ni >> 1] + (ni & 1) * 2);
            }
        }
        __syncthreads();
        cs++; if (cs == NSTAGE) cs = 0;
    }

    float* Cf = (float*)Cout;
    __half* Ch = (__half*)Cout;
#pragma unroll
    for (int mi = 0; mi < 4; mi++) {
        const int row0 = m0 + wm * 64 + mi * 16 + g;
#pragma unroll
        for (int ni = 0; ni < 4; ni++) {
            const int col = n0 + wn * 32 + ni * 8 + t4 * 2;
            const float b0 = bias[col], b1 = bias[col + 1];
            float v0 = acc[mi][ni][0] + b0;
            float v1 = acc[mi][ni][1] + b1;
            float v2 = acc[mi][ni][2] + b0;
            float v3 = acc[mi][ni][3] + b1;
            if (EPI == 1) {
                v0 = 0.5f * v0 * (1.0f + erff(v0 * 0.70710678118654752f));
                v1 = 0.5f * v1 * (1.0f + erff(v1 * 0.70710678118654752f));
                v2 = 0.5f * v2 * (1.0f + erff(v2 * 0.70710678118654752f));
                v3 = 0.5f * v3 * (1.0f + erff(v3 * 0.70710678118654752f));
            } else if (EPI == 2) {
                const float2 r0 = *(const float2*)(res + (size_t)row0 * N + col);
                const float2 r1 = *(const float2*)(res + (size_t)(row0 + 8) * N + col);
                v0 += r0.x; v1 += r0.y; v2 += r1.x; v3 += r1.y;
            }
            if (HOUT) {
                *(__half2*)(Ch + (size_t)row0 * N + col) = __floats2half2_rn(v0, v1);
                *(__half2*)(Ch + (size_t)(row0 + 8) * N + col) = __floats2half2_rn(v2, v3);
            } else {
                *(float2*)(Cf + (size_t)row0 * N + col) = make_float2(v0, v1);
                *(float2*)(Cf + (size_t)(row0 + 8) * N + col) = make_float2(v2, v3);
            }
        }
    }
}

// ---------------------------------------------------------------------------
// Merged weight prep: all 6 transposes in ONE kernel (fp32 -> fp16^T).
// ---------------------------------------------------------------------------
__global__ __launch_bounds__(256)
void prep_weights(const float* __restrict__ Wq, const float* __restrict__ Wk,
                  const float* __restrict__ Wv, const float* __restrict__ Wo,
                  const float* __restrict__ W1, const float* __restrict__ W2,
                  __half* __restrict__ WqkvT, __half* __restrict__ WoT,
                  __half* __restrict__ W1T, __half* __restrict__ W2T)
{
    const int b = blockIdx.x;
    const float* in;
    __half* out;
    int R, C, tile;
    if (b < 4096) {
        const int w = b >> 10;
        tile = b & 1023;
        R = 1024; C = 1024;
        in  = (w == 0) ? Wq : (w == 1) ? Wk : (w == 2) ? Wv : Wo;
        out = (w < 3) ? WqkvT + (size_t)w * 1024 * 1024 : WoT;
    } else if (b < 8192) {
        tile = b - 4096; R = 1024; C = 4096; in = W1; out = W1T;
    } else {
        tile = b - 8192; R = 4096; C = 1024; in = W2; out = W2T;
    }
    const int tcx = C >> 5;
    const int c0 = (tile % tcx) * 32, r0 = (tile / tcx) * 32;

    __shared__ float t[32][33];
    const int tx = threadIdx.x & 31, ty = threadIdx.x >> 5;
#pragma unroll
    for (int i = ty; i < 32; i += 8)
        t[i][tx] = in[(size_t)(r0 + i) * C + c0 + tx];
    __syncthreads();
#pragma unroll
    for (int i = ty; i < 32; i += 8)
        out[(size_t)(c0 + i) * R + r0 + tx] = __float2half_rn(t[tx][i]);
}

__global__ void bias_concat_kernel(const float* __restrict__ bq,
                                   const float* __restrict__ bk,
                                   const float* __restrict__ bv,
                                   float* __restrict__ bqkv)
{
    const int i = blockIdx.x * 256 + threadIdx.x;
    if (i < DDIM) bqkv[i] = bq[i];
    else if (i < 2 * DDIM) bqkv[i] = bk[i - DDIM];
    else bqkv[i] = bv[i - 2 * DDIM];
}

__global__ __launch_bounds__(256)
void f2h_kernel(const float* __restrict__ in, __half* __restrict__ out)
{
    const int i = blockIdx.x * 256 + threadIdx.x;
    const float4 v = ((const float4*)in)[i];
    ((__half2*)out)[2 * i]     = __floats2half2_rn(v.x, v.y);
    ((__half2*)out)[2 * i + 1] = __floats2half2_rn(v.z, v.w);
}

// ---------------------------------------------------------------------------
// fp16 tensor-core flash attention (no scaling). ldmatrix for K and V frags.
// ---------------------------------------------------------------------------
#define SPW 68            // P stride in 32-bit words (136 halfs)
#define NKB (SEQ / 128)
#define AT_P_BYTES (128 * 136 * 2)
#define AT_K_BYTES (2 * 128 * 144)
#define AT_SMEM (AT_P_BYTES + 2 * AT_K_BYTES)

__global__ __launch_bounds__(256)
void attn_h_kernel(const __half* __restrict__ QKV, __half* __restrict__ O)
{
    extern __shared__ char smc[];
    __half* sP = (__half*)smc;                       // [128][136]
    const uint32_t sP_u = smem_u32(sP);
    const uint32_t sK_u = sP_u + AT_P_BYTES;
    const uint32_t sV_u = sK_u + AT_K_BYTES;
    __half* sQstage = sP;                            // Q staged at stride 72

    const int bz   = blockIdx.z;
    const int h    = blockIdx.y;
    const int q0   = blockIdx.x * 128;
    const int tid  = threadIdx.x;
    const int warp = tid >> 5;
    const int lane = tid & 31;
    const int g    = lane >> 2;
    const int t4   = lane & 3;

    const size_t base = (size_t)bz * SEQ;
    const __half* Qg = QKV + (base + q0) * QKVD + h * HDIM;
    const __half* Kg = QKV + base * QKVD + DDIM + h * HDIM;
    const __half* Vg = QKV + base * QKVD + 2 * DDIM + h * HDIM;

    for (int i = tid; i < 128 * 8; i += 256) {
        const int r = i >> 3, c = (i & 7) * 8;
        *(uint4*)(sQstage + r * 72 + c) = *(const uint4*)(Qg + (size_t)r * QKVD + c);
    }
    __syncthreads();

    uint32_t qf[4][4];
    {
        const uint32_t* qrow = (const uint32_t*)sQstage + (warp * 16 + g) * 36;
#pragma unroll
        for (int ks = 0; ks < 4; ks++) {
            qf[ks][0] = qrow[ks * 8 + t4];
            qf[ks][1] = qrow[8 * 36 + ks * 8 + t4];
            qf[ks][2] = qrow[ks * 8 + t4 + 4];
            qf[ks][3] = qrow[8 * 36 + ks * 8 + t4 + 4];
        }
    }
    __syncthreads();

    float oacc[8][4];
#pragma unroll
    for (int n = 0; n < 8; n++)
#pragma unroll
        for (int r = 0; r < 4; r++) oacc[n][r] = 0.0f;
    float m0 = -1e30f, m1 = -1e30f, l0 = 0.0f, l1 = 0.0f;

    const uint32_t kLane = (uint32_t)(((lane >> 4) * 8 + (lane & 7)) * 144 +
                                      ((lane >> 3) & 1) * 16);
    const int lmat = lane >> 3;
    const int lrow = lane & 7;
    const uint32_t vLane = (uint32_t)(((lmat & 1) * 8 + lrow) * 144 +
                                      ((lmat >> 1) * 8) * 2);

#pragma unroll
    for (int i = 0; i < 4; i++) {
        const int idx = tid + i * 256;
        const int r = idx >> 3, c = (idx & 7) * 8;
        cp_async16(sK_u + (uint32_t)(r * 144 + c * 2), Kg + (size_t)r * QKVD + c);
        cp_async16(sV_u + (uint32_t)(r * 144 + c * 2), Vg + (size_t)r * QKVD + c);
    }
    cp_commit();

    for (int kb = 0; kb < NKB; kb++) {
        const int buf = kb & 1;

        if (kb + 1 < NKB) {
            const __half* Kt = Kg + (size_t)(kb + 1) * 128 * QKVD;
            const __half* Vt = Vg + (size_t)(kb + 1) * 128 * QKVD;
            const uint32_t so = (uint32_t)((buf ^ 1) * 128 * 144);
#pragma unroll
            for (int i = 0; i < 4; i++) {
                const int idx = tid + i * 256;
                const int r = idx >> 3, c = (idx & 7) * 8;
                cp_async16(sK_u + so + (uint32_t)(r * 144 + c * 2),
                           Kt + (size_t)r * QKVD + c);
                cp_async16(sV_u + so + (uint32_t)(r * 144 + c * 2),
                           Vt + (size_t)r * QKVD + c);
            }
            cp_commit();
            cp_wait1();
        } else {
            cp_wait0();
        }
        __syncthreads();

        float sc[16][4];
#pragma unroll
        for (int nt = 0; nt < 16; nt++) {
#pragma unroll
            for (int r = 0; r < 4; r++) sc[nt][r] = 0.0f;
        }
        const uint32_t kBase = sK_u + (uint32_t)(buf * 128 * 144) + kLane;
#pragma unroll
        for (int p = 0; p < 8; p++) {
            const uint32_t kp = kBase + (uint32_t)(p * 16 * 144);
#pragma unroll
            for (int ks = 0; ks < 4; ks++) {
                uint32_t kf[4];
                ldmx4(kf, kp + ks * 32);
                mma_f16(sc[2 * p],     qf[ks], kf);
                mma_f16(sc[2 * p + 1], qf[ks], kf + 2);
            }
        }

        float mx0 = m0, mx1 = m1;
#pragma unroll
        for (int nt = 0; nt < 16; nt++) {
            mx0 = fmaxf(mx0, fmaxf(sc[nt][0], sc[nt][1]));
            mx1 = fmaxf(mx1, fmaxf(sc[nt][2], sc[nt][3]));
        }
        mx0 = fmaxf(mx0, __shfl_xor_sync(0xffffffffu, mx0, 1));
        mx0 = fmaxf(mx0, __shfl_xor_sync(0xffffffffu, mx0, 2));
        mx1 = fmaxf(mx1, __shfl_xor_sync(0xffffffffu, mx1, 1));
        mx1 = fmaxf(mx1, __shfl_xor_sync(0xffffffffu, mx1, 2));

        const float s0 = fexp(m0 - mx0);
        const float s1 = fexp(m1 - mx1);
        m0 = mx0; m1 = mx1;
        l0 *= s0;  l1 *= s1;
#pragma unroll
        for (int n = 0; n < 8; n++) {
            oacc[n][0] *= s0; oacc[n][1] *= s0;
            oacc[n][2] *= s1; oacc[n][3] *= s1;
        }

        const int prow = warp * 16 + g;
        uint32_t* pw0 = (uint32_t*)sP + prow * SPW;
        uint32_t* pw1 = (uint32_t*)sP + (prow + 8) * SPW;
        float ls0 = 0.0f, ls1 = 0.0f;
#pragma unroll
        for (int nt = 0; nt < 16; nt++) {
            const float p0 = fexp(sc[nt][0] - mx0);
            const float p1 = fexp(sc[nt][1] - mx0);
            const float p2 = fexp(sc[nt][2] - mx1);
            const float p3 = fexp(sc[nt][3] - mx1);
            ls0 += p0 + p1;
            ls1 += p2 + p3;
            const __half2 h01 = __floats2half2_rn(p0, p1);
            const __half2 h23 = __floats2half2_rn(p2, p3);
            pw0[nt * 4 + t4] = *(const uint32_t*)&h01;
            pw1[nt * 4 + t4] = *(const uint32_t*)&h23;
        }
        l0 += ls0; l1 += ls1;
        __syncthreads();

        const uint32_t vBase = sV_u + (uint32_t)(buf * 128 * 144) + vLane;
        const uint32_t* pa0 = (const uint32_t*)sP + prow * SPW + t4;
        const uint32_t* pa1 = (const uint32_t*)sP + (prow + 8) * SPW + t4;
#pragma unroll
        for (int ks = 0; ks < 8; ks++) {
            uint32_t af[4];
            af[0] = pa0[ks * 8];
            af[1] = pa1[ks * 8];
            af[2] = pa0[ks * 8 + 4];
            af[3] = pa1[ks * 8 + 4];
            const uint32_t vks = vBase + (uint32_t)(ks * 16 * 144);
#pragma unroll
            for (int nt2 = 0; nt2 < 4; nt2++) {
                uint32_t vr[4];
                ldmx4_trans(vr, vks + (uint32_t)(nt2 * 32));
                mma_f16(oacc[nt2 * 2],     af, vr);
                mma_f16(oacc[nt2 * 2 + 1], af, vr + 2);
            }
        }
        __syncthreads();
    }

    l0 += __shfl_xor_sync(0xffffffffu, l0, 1);
    l0 += __shfl_xor_sync(0xffffffffu, l0, 2);
    l1 += __shfl_xor_sync(0xffffffffu, l1, 1);
    l1 += __shfl_xor_sync(0xffffffffu, l1, 2);
    const float inv0 = 1.0f / l0;
    const float inv1 = 1.0f / l1;

    const size_t row = base + q0 + warp * 16 + g;
    __half* Og = O + row * DDIM + h * HDIM;
#pragma unroll
    for (int nt = 0; nt < 8; nt++) {
        const int col = nt * 8 + 2 * t4;
        *(__half2*)(Og + col) =
            __floats2half2_rn(oacc[nt][0] * inv0, oacc[nt][1] * inv0);
        *(__half2*)(Og + 8 * DDIM + col) =
            __floats2half2_rn(oacc[nt][2] * inv1, oacc[nt][3] * inv1);
    }
}

// ---------------------------------------------------------------------------
// LayerNorm (D=1024), one block per row, 256 threads, float4 I/O.
// ---------------------------------------------------------------------------
__global__ __launch_bounds__(256)
void ln_kernel(const float* __restrict__ x, const float* __restrict__ g,
               const float* __restrict__ b, float* __restrict__ y,
               __half* __restrict__ yh)
{
    const int D = DDIM;
    const int row = blockIdx.x;
    const float4 v = ((const float4*)(x + (size_t)row * D))[threadIdx.x];

    float s  = v.x + v.y + v.z + v.w;
    float s2 = fmaf(v.x, v.x, fmaf(v.y, v.y, fmaf(v.z, v.z, v.w * v.w)));
#pragma unroll
    for (int o = 16; o > 0; o >>= 1) {
        s  += __shfl_xor_sync(0xffffffffu, s, o);
        s2 += __shfl_xor_sync(0xffffffffu, s2, o);
    }
    __shared__ float ss[8], ss2[8];
    const int w = threadIdx.x >> 5;
    if ((threadIdx.x & 31) == 0) { ss[w] = s; ss2[w] = s2; }
    __syncthreads();
    if (threadIdx.x < 32) {
        s  = (threadIdx.x < 8) ? ss[threadIdx.x]  : 0.f;
        s2 = (threadIdx.x < 8) ? ss2[threadIdx.x] : 0.f;
#pragma unroll
        for (int o = 4; o > 0; o >>= 1) {
            s  += __shfl_xor_sync(0xffffffffu, s, o);
            s2 += __shfl_xor_sync(0xffffffffu, s2, o);
        }
        if (threadIdx.x == 0) { ss[0] = s; ss2[0] = s2; }
    }
    __syncthreads();
    const float mu  = ss[0] * (1.0f / D);
    const float var = ss2[0] * (1.0f / D) - mu * mu;
    const float inv = rsqrtf(var + 1e-5f);

    const float4 gv = ((const float4*)g)[threadIdx.x];
    const float4 bv = ((const float4*)b)[threadIdx.x];
    float4 o4;
    o4.x = (v.x - mu) * inv * gv.x + bv.x;
    o4.y = (v.y - mu) * inv * gv.y + bv.y;
    o4.z = (v.z - mu) * inv * gv.z + bv.z;
    o4.w = (v.w - mu) * inv * gv.w + bv.w;
    ((float4*)(y + (size_t)row * D))[threadIdx.x] = o4;
    if (yh) {
        uint2 hpair;
        __half2 h0 = __floats2half2_rn(o4.x, o4.y);
        __half2 h1 = __floats2half2_rn(o4.z, o4.w);
        hpair.x = *(const uint32_t*)&h0;
        hpair.y = *(const uint32_t*)&h1;
        ((uint2*)(yh + (size_t)row * D))[threadIdx.x] = hpair;
    }
}

// ---------------------------------------------------------------------------
// Launch
// ---------------------------------------------------------------------------
extern "C" void kernel_launch(void* const* d_in, const int* in_sizes, int n_in,
                              void* d_out, int out_size)
{
    (void)in_sizes; (void)n_in; (void)out_size;
    const float* x     = (const float*)d_in[0];
    const float* Wq    = (const float*)d_in[1];
    const float* bq    = (const float*)d_in[2];
    const float* Wk    = (const float*)d_in[3];
    const float* bk    = (const float*)d_in[4];
    const float* Wv    = (const float*)d_in[5];
    const float* bv    = (const float*)d_in[6];
    const float* Wo    = (const float*)d_in[7];
    const float* bo    = (const float*)d_in[8];
    const float* W1    = (const float*)d_in[9];
    const float* b1    = (const float*)d_in[10];
    const float* W2    = (const float*)d_in[11];
    const float* b2    = (const float*)d_in[12];
    const float* g1    = (const float*)d_in[13];
    const float* beta1 = (const float*)d_in[14];
    const float* g2    = (const float*)d_in[15];
    const float* beta2 = (const float*)d_in[16];
    float* out = (float*)d_out;

    float* scr = nullptr;
    cudaGetSymbolAddress((void**)&scr, g_scratch);
    __half* qkvh  = (__half*)(scr + OFF_QKVH);
    float*  x1    = scr + OFF_X1;
    float*  x2    = scr + OFF_X2;
    float*  x3    = scr + OFF_X3;
    __half* atth  = (__half*)(scr + OFF_ATTH);
    __half* x2h   = (__half*)(scr + OFF_X2H);
    __half* hh    = (__half*)(scr + OFF_HH);
    __half* xh    = (__half*)(scr + OFF_XH);
    __half* WqkvT = (__half*)(scr + OFF_WQKVT);
    __half* WoT   = (__half*)(scr + OFF_WOT);
    __half* W1T   = (__half*)(scr + OFF_W1T);
    __half* W2T   = (__half*)(scr + OFF_W2T);
    float*  bqkv  = scr + OFF_BQKV;

    cudaFuncSetAttribute(gemm_h<0,1>, cudaFuncAttributeMaxDynamicSharedMemorySize, GT_SMEM);
    cudaFuncSetAttribute(gemm_h<1,1>, cudaFuncAttributeMaxDynamicSharedMemorySize, GT_SMEM);
    cudaFuncSetAttribute(gemm_h<2,0>, cudaFuncAttributeMaxDynamicSharedMemorySize, GT_SMEM);
    cudaFuncSetAttribute(attn_h_kernel, cudaFuncAttributeMaxDynamicSharedMemorySize, AT_SMEM);

    // prep
    f2h_kernel<<<(MTOK * DDIM / 4) / 256, 256>>>(x, xh);
    prep_weights<<<12288, 256>>>(Wq, Wk, Wv, Wo, W1, W2, WqkvT, WoT, W1T, W2T);
    bias_concat_kernel<<<QKVD / 256, 256>>>(bq, bk, bv, bqkv);

    // fused QKV projection -> fp16
    gemm_h<0,1><<<dim3(QKVD / BN, MTOK / BM), 256, GT_SMEM>>>(
        xh, WqkvT, bqkv, nullptr, qkvh, MTOK, QKVD, DDIM);

    // attention (fp16 tensor cores, no scaling)
    attn_h_kernel<<<dim3(SEQ / 128, NHEAD, BATCH), 256, AT_SMEM>>>(qkvh, atth);

    // output projection + residual
    gemm_h<2,0><<<dim3(DDIM / BN, MTOK / BM), 256, GT_SMEM>>>(
        atth, WoT, bo, x, x1, MTOK, DDIM, DDIM);

    // LN1
    ln_kernel<<<MTOK, 256>>>(x1, g1, beta1, x2, x2h);

    // FFN
    gemm_h<1,1><<<dim3(FFDIM / BN, MTOK / BM), 256, GT_SMEM>>>(
        x2h, W1T, b1, nullptr, hh, MTOK, FFDIM, DDIM);
    gemm_h<2,0><<<dim3(DDIM / BN, MTOK / BM), 256, GT_SMEM>>>(
        hh, W2T, b2, x2, x3, MTOK, DDIM, FFDIM);

    // LN2 -> output
    ln_kernel<<<MTOK, 256>>>(x3, g2, beta2, out, nullptr);
}

// round 15
// speedup vs baseline: 1.0768x; 1.0768x over previous
#include <cuda_runtime.h>
#include <cuda_fp16.h>
#include <math.h>
#include <cstdint>

// ---------------------------------------------------------------------------
// Transformer block. All GEMMs + attention via mma.sync fp16 (fp32 accum).
// GEMM: R11-best config (128x128, BK=32, double buffer). Attention: P kept
// in registers (no smem round-trip). M=4096, D=1024, H=16, hd=64, FF=4096.
// ---------------------------------------------------------------------------

#define MTOK 4096
#define DDIM 1024
#define QKVD 3072
#define FFDIM 4096
#define NHEAD 16
#define HDIM 64
#define SEQ 2048
#define BATCH 2

// scratch layout (units: floats)
#define OFF_QKVH  ((size_t)0)
#define OFF_X1    (OFF_QKVH + (size_t)MTOK*QKVD/2)
#define OFF_X2    (OFF_X1   + (size_t)MTOK*DDIM)
#define OFF_X3    (OFF_X2   + (size_t)MTOK*DDIM)
#define OFF_ATTH  (OFF_X3   + (size_t)MTOK*DDIM)
#define OFF_X2H   (OFF_ATTH + (size_t)MTOK*DDIM/2)
#define OFF_HH    (OFF_X2H  + (size_t)MTOK*DDIM/2)
#define OFF_XH    (OFF_HH   + (size_t)MTOK*FFDIM/2)
#define OFF_WQKVT (OFF_XH   + (size_t)MTOK*DDIM/2)
#define OFF_WOT   (OFF_WQKVT+ (size_t)QKVD*DDIM/2)
#define OFF_W1T   (OFF_WOT  + (size_t)DDIM*DDIM/2)
#define OFF_W2T   (OFF_W1T  + (size_t)DDIM*FFDIM/2)
#define OFF_BQKV  (OFF_W2T  + (size_t)FFDIM*DDIM/2)
#define SCRATCH_FLOATS (OFF_BQKV + (size_t)QKVD)

__device__ float g_scratch[SCRATCH_FLOATS];

// ---------------- PTX helpers ----------------
__device__ __forceinline__ void cp_async16(uint32_t dst, const void* src) {
    asm volatile("cp.async.cg.shared.global [%0], [%1], 16;"
                 :: "r"(dst), "l"(src) : "memory");
}
__device__ __forceinline__ void cp_commit() {
    asm volatile("cp.async.commit_group;" ::: "memory");
}
__device__ __forceinline__ void cp_wait0() {
    asm volatile("cp.async.wait_group 0;" ::: "memory");
}
__device__ __forceinline__ void cp_wait1() {
    asm volatile("cp.async.wait_group 1;" ::: "memory");
}
__device__ __forceinline__ uint32_t smem_u32(const void* p) {
    uint32_t a;
    asm("{ .reg .u64 t; cvta.to.shared.u64 t, %1; cvt.u32.u64 %0, t; }"
        : "=r"(a) : "l"(p));
    return a;
}
__device__ __forceinline__ void mma_f16(float* c, const uint32_t* a,
                                        const uint32_t* b) {
    asm volatile(
        "mma.sync.aligned.m16n8k16.row.col.f32.f16.f16.f32 "
        "{%0,%1,%2,%3}, {%4,%5,%6,%7}, {%8,%9}, {%0,%1,%2,%3};"
        : "+f"(c[0]), "+f"(c[1]), "+f"(c[2]), "+f"(c[3])
        : "r"(a[0]), "r"(a[1]), "r"(a[2]), "r"(a[3]), "r"(b[0]), "r"(b[1]));
}
__device__ __forceinline__ void ldmx4(uint32_t* r, uint32_t addr) {
    asm volatile(
        "ldmatrix.sync.aligned.m8n8.x4.shared.b16 {%0,%1,%2,%3}, [%4];"
        : "=r"(r[0]), "=r"(r[1]), "=r"(r[2]), "=r"(r[3]) : "r"(addr));
}
__device__ __forceinline__ void ldmx4_trans(uint32_t* r, uint32_t addr) {
    asm volatile(
        "ldmatrix.sync.aligned.m8n8.x4.trans.shared.b16 {%0,%1,%2,%3}, [%4];"
        : "=r"(r[0]), "=r"(r[1]), "=r"(r[2]), "=r"(r[3]) : "r"(addr));
}

// Fast exp on the FMA pipe (no MUFU).
__device__ __forceinline__ float fexp(float x) {
    float t = x * 1.4426950408889634f;
    t = fmaxf(t, -126.0f);
    const float fn = rintf(t);
    const float f = t - fn;
    float p = 1.33336500e-3f;
    p = fmaf(p, f, 9.61823766e-3f);
    p = fmaf(p, f, 5.55041087e-2f);
    p = fmaf(p, f, 2.40226507e-1f);
    p = fmaf(p, f, 6.93147182e-1f);
    p = fmaf(p, f, 1.0f);
    const int n = (int)fn;
    return p * __int_as_float((n + 127) << 23);
}

// ---------------------------------------------------------------------------
// fp16 GEMM (R11 config): C = A @ Bt^T + bias (+ epilogue)
// CTA 128x128, BK=32 halfs, 256 threads, double-buffered cp.async,
// ldmatrix.x4 fragment loads (144 B row stride, conflict-free).
// ---------------------------------------------------------------------------
#define BM 128
#define BN 128
#define ATILE_B (128 * 144)
#define BTILE_B (128 * 144)
#define GT_SMEM (2 * ATILE_B + 2 * BTILE_B)   // 73728

template <int EPI, int HOUT>
__global__ __launch_bounds__(256, 2)
void gemm_h(const __half* __restrict__ A, const __half* __restrict__ Bt,
            const float* __restrict__ bias, const float* __restrict__ res,
            void* __restrict__ Cout, int M, int N, int K)
{
    extern __shared__ __half smh[];
    const uint32_t As_u = smem_u32(smh);
    const uint32_t Bs_u = As_u + 2 * ATILE_B;

    const int tid  = threadIdx.x;
    const int warp = tid >> 5;
    const int lane = tid & 31;
    const int g    = lane >> 2;
    const int t4   = lane & 3;
    const int wm   = warp >> 2;
    const int wn   = warp & 3;

    const int m0 = blockIdx.y * BM;
    const int n0 = blockIdx.x * BN;

    const int lrow = tid >> 1;
    const int l16  = (tid & 1) * 2;
    const __half* Ag = A + (size_t)(m0 + lrow) * K + l16 * 8;
    const __half* Bg = Bt + (size_t)(n0 + lrow) * K + l16 * 8;
    const uint32_t Asm = As_u + (uint32_t)(lrow * 144 + l16 * 16);
    const uint32_t Bsm = Bs_u + (uint32_t)(lrow * 144 + l16 * 16);

    const uint32_t aLane = (uint32_t)((wm * 64 + (lane & 15)) * 144 +
                                      (lane >> 4) * 16);
    const uint32_t bLane = (uint32_t)((wn * 32 + (lane >> 4) * 8 + (lane & 7)) * 144 +
                                      ((lane >> 3) & 1) * 16);

    float acc[4][4][4];
#pragma unroll
    for (int mi = 0; mi < 4; mi++)
#pragma unroll
        for (int ni = 0; ni < 4; ni++)
#pragma unroll
            for (int r = 0; r < 4; r++) acc[mi][ni][r] = 0.0f;

    const int T = K >> 5;

    cp_async16(Asm, Ag);
    cp_async16(Asm + 16, Ag + 8);
    cp_async16(Bsm, Bg);
    cp_async16(Bsm + 16, Bg + 8);
    cp_commit();

    for (int tb = 0; tb < T; tb++) {
        const int b = tb & 1;
        if (tb + 1 < T) {
            const uint32_t ao = (uint32_t)((b ^ 1) * ATILE_B);
            const uint32_t bo = (uint32_t)((b ^ 1) * BTILE_B);
            const size_t ko = (size_t)(tb + 1) * 32;
            cp_async16(Asm + ao, Ag + ko);
            cp_async16(Asm + ao + 16, Ag + ko + 8);
            cp_async16(Bsm + bo, Bg + ko);
            cp_async16(Bsm + bo + 16, Bg + ko + 8);
            cp_commit();
            cp_wait1();
        } else {
            cp_wait0();
        }
        __syncthreads();

        const uint32_t aBase = As_u + (uint32_t)(b * ATILE_B) + aLane;
        const uint32_t bBase = Bs_u + (uint32_t)(b * BTILE_B) + bLane;
#pragma unroll
        for (int kk = 0; kk < 2; kk++) {
            uint32_t af[4][4], bf4[2][4];
#pragma unroll
            for (int mi = 0; mi < 4; mi++)
                ldmx4(af[mi], aBase + mi * (16 * 144) + kk * 32);
#pragma unroll
            for (int p = 0; p < 2; p++)
                ldmx4(bf4[p], bBase + p * (16 * 144) + kk * 32);
#pragma unroll
            for (int mi = 0; mi < 4; mi++)
#pragma unroll
                for (int ni = 0; ni < 4; ni++)
                    mma_f16(acc[mi][ni], af[mi], bf4[ni >> 1] + (ni & 1) * 2);
        }
        __syncthreads();
    }

    float* Cf = (float*)Cout;
    __half* Ch = (__half*)Cout;
#pragma unroll
    for (int mi = 0; mi < 4; mi++) {
        const int row0 = m0 + wm * 64 + mi * 16 + g;
#pragma unroll
        for (int ni = 0; ni < 4; ni++) {
            const int col = n0 + wn * 32 + ni * 8 + t4 * 2;
            const float b0 = bias[col], b1 = bias[col + 1];
            float v0 = acc[mi][ni][0] + b0;
            float v1 = acc[mi][ni][1] + b1;
            float v2 = acc[mi][ni][2] + b0;
            float v3 = acc[mi][ni][3] + b1;
            if (EPI == 1) {
                v0 = 0.5f * v0 * (1.0f + erff(v0 * 0.70710678118654752f));
                v1 = 0.5f * v1 * (1.0f + erff(v1 * 0.70710678118654752f));
                v2 = 0.5f * v2 * (1.0f + erff(v2 * 0.70710678118654752f));
                v3 = 0.5f * v3 * (1.0f + erff(v3 * 0.70710678118654752f));
            } else if (EPI == 2) {
                const float2 r0 = *(const float2*)(res + (size_t)row0 * N + col);
                const float2 r1 = *(const float2*)(res + (size_t)(row0 + 8) * N + col);
                v0 += r0.x; v1 += r0.y; v2 += r1.x; v3 += r1.y;
            }
            if (HOUT) {
                *(__half2*)(Ch + (size_t)row0 * N + col) = __floats2half2_rn(v0, v1);
                *(__half2*)(Ch + (size_t)(row0 + 8) * N + col) = __floats2half2_rn(v2, v3);
            } else {
                *(float2*)(Cf + (size_t)row0 * N + col) = make_float2(v0, v1);
                *(float2*)(Cf + (size_t)(row0 + 8) * N + col) = make_float2(v2, v3);
            }
        }
    }
}

// ---------------------------------------------------------------------------
// Merged prep: weight transposes + x->fp16 + bias concat in ONE kernel.
// blocks [0,12288): transposes; [12288,16384): f2h of x; [16384,16396): bias.
// ---------------------------------------------------------------------------
__global__ __launch_bounds__(256)
void prep_all(const float* __restrict__ x, const float* __restrict__ Wq,
              const float* __restrict__ Wk, const float* __restrict__ Wv,
              const float* __restrict__ Wo, const float* __restrict__ W1,
              const float* __restrict__ W2, const float* __restrict__ bq,
              const float* __restrict__ bk, const float* __restrict__ bv,
              __half* __restrict__ xh, __half* __restrict__ WqkvT,
              __half* __restrict__ WoT, __half* __restrict__ W1T,
              __half* __restrict__ W2T, float* __restrict__ bqkv)
{
    const int b = blockIdx.x;
    if (b >= 16384) {       // bias concat: 12 blocks x 256 = 3072
        const int i = (b - 16384) * 256 + threadIdx.x;
        if (i < DDIM) bqkv[i] = bq[i];
        else if (i < 2 * DDIM) bqkv[i] = bk[i - DDIM];
        else bqkv[i] = bv[i - 2 * DDIM];
        return;
    }
    if (b >= 12288) {       // f2h: 4096 blocks x 256 thr x 4 floats
        const int i = (b - 12288) * 256 + threadIdx.x;
        const float4 v = ((const float4*)x)[i];
        ((__half2*)xh)[2 * i]     = __floats2half2_rn(v.x, v.y);
        ((__half2*)xh)[2 * i + 1] = __floats2half2_rn(v.z, v.w);
        return;
    }
    const float* in;
    __half* out;
    int R, C, tile;
    if (b < 4096) {
        const int w = b >> 10;
        tile = b & 1023;
        R = 1024; C = 1024;
        in  = (w == 0) ? Wq : (w == 1) ? Wk : (w == 2) ? Wv : Wo;
        out = (w < 3) ? WqkvT + (size_t)w * 1024 * 1024 : WoT;
    } else if (b < 8192) {
        tile = b - 4096; R = 1024; C = 4096; in = W1; out = W1T;
    } else {
        tile = b - 8192; R = 4096; C = 1024; in = W2; out = W2T;
    }
    const int tcx = C >> 5;
    const int c0 = (tile % tcx) * 32, r0 = (tile / tcx) * 32;

    __shared__ float t[32][33];
    const int tx = threadIdx.x & 31, ty = threadIdx.x >> 5;
#pragma unroll
    for (int i = ty; i < 32; i += 8)
        t[i][tx] = in[(size_t)(r0 + i) * C + c0 + tx];
    __syncthreads();
#pragma unroll
    for (int i = ty; i < 32; i += 8)
        out[(size_t)(c0 + i) * R + r0 + tx] = __float2half_rn(t[tx][i]);
}

// ---------------------------------------------------------------------------
// fp16 tensor-core flash attention (no scaling). P stays in registers:
// S accumulator fragments map directly onto P@V A-fragments. One barrier
// pair per key tile. smem: K/V [2][128][72]h only (Q staged through sK).
// ---------------------------------------------------------------------------
#define NKB (SEQ / 128)
#define AT_K_BYTES (2 * 128 * 144)
#define AT_SMEM (2 * AT_K_BYTES)   // 73728

__global__ __launch_bounds__(256, 2)
void attn_h_kernel(const __half* __restrict__ QKV, __half* __restrict__ O)
{
    extern __shared__ char smc[];
    const uint32_t sK_u = smem_u32(smc);
    const uint32_t sV_u = sK_u + AT_K_BYTES;
    __half* sQstage = (__half*)smc;      // Q staged in sK region, stride 72

    const int bz   = blockIdx.z;
    const int h    = blockIdx.y;
    const int q0   = blockIdx.x * 128;
    const int tid  = threadIdx.x;
    const int warp = tid >> 5;
    const int lane = tid & 31;
    const int g    = lane >> 2;
    const int t4   = lane & 3;

    const size_t base = (size_t)bz * SEQ;
    const __half* Qg = QKV + (base + q0) * QKVD + h * HDIM;
    const __half* Kg = QKV + base * QKVD + DDIM + h * HDIM;
    const __half* Vg = QKV + base * QKVD + 2 * DDIM + h * HDIM;

    // stage Q tile [128][64]h into sK region (stride 72 halfs)
    for (int i = tid; i < 128 * 8; i += 256) {
        const int r = i >> 3, c = (i & 7) * 8;
        *(uint4*)(sQstage + r * 72 + c) = *(const uint4*)(Qg + (size_t)r * QKVD + c);
    }
    __syncthreads();

    uint32_t qf[4][4];
    {
        const uint32_t* qrow = (const uint32_t*)sQstage + (warp * 16 + g) * 36;
#pragma unroll
        for (int ks = 0; ks < 4; ks++) {
            qf[ks][0] = qrow[ks * 8 + t4];
            qf[ks][1] = qrow[8 * 36 + ks * 8 + t4];
            qf[ks][2] = qrow[ks * 8 + t4 + 4];
            qf[ks][3] = qrow[8 * 36 + ks * 8 + t4 + 4];
        }
    }
    __syncthreads();   // Q fragments extracted; sK region free for K tiles

    float oacc[8][4];
#pragma unroll
    for (int n = 0; n < 8; n++)
#pragma unroll
        for (int r = 0; r < 4; r++) oacc[n][r] = 0.0f;
    float m0 = -1e30f, m1 = -1e30f, l0 = 0.0f, l1 = 0.0f;

    const uint32_t kLane = (uint32_t)(((lane >> 4) * 8 + (lane & 7)) * 144 +
                                      ((lane >> 3) & 1) * 16);
    const int lmat = lane >> 3;
    const int lrow = lane & 7;
    const uint32_t vLane = (uint32_t)(((lmat & 1) * 8 + lrow) * 144 +
                                      ((lmat >> 1) * 8) * 2);

    // prologue K/V tiles
#pragma unroll
    for (int i = 0; i < 4; i++) {
        const int idx = tid + i * 256;
        const int r = idx >> 3, c = (idx & 7) * 8;
        cp_async16(sK_u + (uint32_t)(r * 144 + c * 2), Kg + (size_t)r * QKVD + c);
        cp_async16(sV_u + (uint32_t)(r * 144 + c * 2), Vg + (size_t)r * QKVD + c);
    }
    cp_commit();

    for (int kb = 0; kb < NKB; kb++) {
        const int buf = kb & 1;

        if (kb + 1 < NKB) {
            const __half* Kt = Kg + (size_t)(kb + 1) * 128 * QKVD;
            const __half* Vt = Vg + (size_t)(kb + 1) * 128 * QKVD;
            const uint32_t so = (uint32_t)((buf ^ 1) * 128 * 144);
#pragma unroll
            for (int i = 0; i < 4; i++) {
                const int idx = tid + i * 256;
                const int r = idx >> 3, c = (idx & 7) * 8;
                cp_async16(sK_u + so + (uint32_t)(r * 144 + c * 2),
                           Kt + (size_t)r * QKVD + c);
                cp_async16(sV_u + so + (uint32_t)(r * 144 + c * 2),
                           Vt + (size_t)r * QKVD + c);
            }
            cp_commit();
            cp_wait1();
        } else {
            cp_wait0();
        }
        __syncthreads();

        // ---- S = Q @ K^T (16 x 128 per warp) ----
        float sc[16][4];
#pragma unroll
        for (int nt = 0; nt < 16; nt++) {
#pragma unroll
            for (int r = 0; r < 4; r++) sc[nt][r] = 0.0f;
        }
        const uint32_t kBase = sK_u + (uint32_t)(buf * 128 * 144) + kLane;
#pragma unroll
        for (int p = 0; p < 8; p++) {
            const uint32_t kp = kBase + (uint32_t)(p * 16 * 144);
#pragma unroll
            for (int ks = 0; ks < 4; ks++) {
                uint32_t kf[4];
                ldmx4(kf, kp + ks * 32);
                mma_f16(sc[2 * p],     qf[ks], kf);
                mma_f16(sc[2 * p + 1], qf[ks], kf + 2);
            }
        }

        // ---- online softmax (row max across quad) ----
        float mx0 = m0, mx1 = m1;
#pragma unroll
        for (int nt = 0; nt < 16; nt++) {
            mx0 = fmaxf(mx0, fmaxf(sc[nt][0], sc[nt][1]));
            mx1 = fmaxf(mx1, fmaxf(sc[nt][2], sc[nt][3]));
        }
        mx0 = fmaxf(mx0, __shfl_xor_sync(0xffffffffu, mx0, 1));
        mx0 = fmaxf(mx0, __shfl_xor_sync(0xffffffffu, mx0, 2));
        mx1 = fmaxf(mx1, __shfl_xor_sync(0xffffffffu, mx1, 1));
        mx1 = fmaxf(mx1, __shfl_xor_sync(0xffffffffu, mx1, 2));

        const float s0 = fexp(m0 - mx0);
        const float s1 = fexp(m1 - mx1);
        m0 = mx0; m1 = mx1;
        l0 *= s0;  l1 *= s1;
#pragma unroll
        for (int n = 0; n < 8; n++) {
            oacc[n][0] *= s0; oacc[n][1] *= s0;
            oacc[n][2] *= s1; oacc[n][3] *= s1;
        }

        // ---- fused P conversion + P @ V (P never touches smem) ----
        // S frag (c0,c1)@row g / (c2,c3)@row g+8 of ntile nt == P A-frag
        // pairs for kstep ks = nt/2: af = {P[2ks].01, P[2ks].23,
        //                                  P[2ks+1].01, P[2ks+1].23}.
        const uint32_t vBase = sV_u + (uint32_t)(buf * 128 * 144) + vLane;
        float ls0 = 0.0f, ls1 = 0.0f;
#pragma unroll
        for (int ks = 0; ks < 8; ks++) {
            uint32_t af[4];
            {
                const float p0 = fexp(sc[2 * ks][0] - mx0);
                const float p1 = fexp(sc[2 * ks][1] - mx0);
                const float p2 = fexp(sc[2 * ks][2] - mx1);
                const float p3 = fexp(sc[2 * ks][3] - mx1);
                ls0 += p0 + p1; ls1 += p2 + p3;
                const __half2 h01 = __floats2half2_rn(p0, p1);
                const __half2 h23 = __floats2half2_rn(p2, p3);
                af[0] = *(const uint32_t*)&h01;
                af[1] = *(const uint32_t*)&h23;
                const float q0 = fexp(sc[2 * ks + 1][0] - mx0);
                const float q1 = fexp(sc[2 * ks + 1][1] - mx0);
                const float q2 = fexp(sc[2 * ks + 1][2] - mx1);
                const float q3 = fexp(sc[2 * ks + 1][3] - mx1);
                ls0 += q0 + q1; ls1 += q2 + q3;
                const __half2 g01 = __floats2half2_rn(q0, q1);
                const __half2 g23 = __floats2half2_rn(q2, q3);
                af[2] = *(const uint32_t*)&g01;
                af[3] = *(const uint32_t*)&g23;
            }
            const uint32_t vks = vBase + (uint32_t)(ks * 16 * 144);
#pragma unroll
            for (int nt2 = 0; nt2 < 4; nt2++) {
                uint32_t vr[4];
                ldmx4_trans(vr, vks + (uint32_t)(nt2 * 32));
                mma_f16(oacc[nt2 * 2],     af, vr);
                mma_f16(oacc[nt2 * 2 + 1], af, vr + 2);
            }
        }
        l0 += ls0; l1 += ls1;
        __syncthreads();   // protect K/V buffers before next prefetch
    }

    l0 += __shfl_xor_sync(0xffffffffu, l0, 1);
    l0 += __shfl_xor_sync(0xffffffffu, l0, 2);
    l1 += __shfl_xor_sync(0xffffffffu, l1, 1);
    l1 += __shfl_xor_sync(0xffffffffu, l1, 2);
    const float inv0 = 1.0f / l0;
    const float inv1 = 1.0f / l1;

    const size_t row = base + q0 + warp * 16 + g;
    __half* Og = O + row * DDIM + h * HDIM;
#pragma unroll
    for (int nt = 0; nt < 8; nt++) {
        const int col = nt * 8 + 2 * t4;
        *(__half2*)(Og + col) =
            __floats2half2_rn(oacc[nt][0] * inv0, oacc[nt][1] * inv0);
        *(__half2*)(Og + 8 * DDIM + col) =
            __floats2half2_rn(oacc[nt][2] * inv1, oacc[nt][3] * inv1);
    }
}

// ---------------------------------------------------------------------------
// LayerNorm (D=1024), one block per row, 256 threads, float4 I/O.
// ---------------------------------------------------------------------------
__global__ __launch_bounds__(256)
void ln_kernel(const float* __restrict__ x, const float* __restrict__ g,
               const float* __restrict__ b, float* __restrict__ y,
               __half* __restrict__ yh)
{
    const int D = DDIM;
    const int row = blockIdx.x;
    const float4 v = ((const float4*)(x + (size_t)row * D))[threadIdx.x];

    float s  = v.x + v.y + v.z + v.w;
    float s2 = fmaf(v.x, v.x, fmaf(v.y, v.y, fmaf(v.z, v.z, v.w * v.w)));
#pragma unroll
    for (int o = 16; o > 0; o >>= 1) {
        s  += __shfl_xor_sync(0xffffffffu, s, o);
        s2 += __shfl_xor_sync(0xffffffffu, s2, o);
    }
    __shared__ float ss[8], ss2[8];
    const int w = threadIdx.x >> 5;
    if ((threadIdx.x & 31) == 0) { ss[w] = s; ss2[w] = s2; }
    __syncthreads();
    if (threadIdx.x < 32) {
        s  = (threadIdx.x < 8) ? ss[threadIdx.x]  : 0.f;
        s2 = (threadIdx.x < 8) ? ss2[threadIdx.x] : 0.f;
#pragma unroll
        for (int o = 4; o > 0; o >>= 1) {
            s  += __shfl_xor_sync(0xffffffffu, s, o);
            s2 += __shfl_xor_sync(0xffffffffu, s2, o);
        }
        if (threadIdx.x == 0) { ss[0] = s; ss2[0] = s2; }
    }
    __syncthreads();
    const float mu  = ss[0] * (1.0f / D);
    const float var = ss2[0] * (1.0f / D) - mu * mu;
    const float inv = rsqrtf(var + 1e-5f);

    const float4 gv = ((const float4*)g)[threadIdx.x];
    const float4 bv = ((const float4*)b)[threadIdx.x];
    float4 o4;
    o4.x = (v.x - mu) * inv * gv.x + bv.x;
    o4.y = (v.y - mu) * inv * gv.y + bv.y;
    o4.z = (v.z - mu) * inv * gv.z + bv.z;
    o4.w = (v.w - mu) * inv * gv.w + bv.w;
    ((float4*)(y + (size_t)row * D))[threadIdx.x] = o4;
    if (yh) {
        uint2 hpair;
        __half2 h0 = __floats2half2_rn(o4.x, o4.y);
        __half2 h1 = __floats2half2_rn(o4.z, o4.w);
        hpair.x = *(const uint32_t*)&h0;
        hpair.y = *(const uint32_t*)&h1;
        ((uint2*)(yh + (size_t)row * D))[threadIdx.x] = hpair;
    }
}

// ---------------------------------------------------------------------------
// Launch
// ---------------------------------------------------------------------------
extern "C" void kernel_launch(void* const* d_in, const int* in_sizes, int n_in,
                              void* d_out, int out_size)
{
    (void)in_sizes; (void)n_in; (void)out_size;
    const float* x     = (const float*)d_in[0];
    const float* Wq    = (const float*)d_in[1];
    const float* bq    = (const float*)d_in[2];
    const float* Wk    = (const float*)d_in[3];
    const float* bk    = (const float*)d_in[4];
    const float* Wv    = (const float*)d_in[5];
    const float* bv    = (const float*)d_in[6];
    const float* Wo    = (const float*)d_in[7];
    const float* bo    = (const float*)d_in[8];
    const float* W1    = (const float*)d_in[9];
    const float* b1    = (const float*)d_in[10];
    const float* W2    = (const float*)d_in[11];
    const float* b2    = (const float*)d_in[12];
    const float* g1    = (const float*)d_in[13];
    const float* beta1 = (const float*)d_in[14];
    const float* g2    = (const float*)d_in[15];
    const float* beta2 = (const float*)d_in[16];
    float* out = (float*)d_out;

    float* scr = nullptr;
    cudaGetSymbolAddress((void**)&scr, g_scratch);
    __half* qkvh  = (__half*)(scr + OFF_QKVH);
    float*  x1    = scr + OFF_X1;
    float*  x2    = scr + OFF_X2;
    float*  x3    = scr + OFF_X3;
    __half* atth  = (__half*)(scr + OFF_ATTH);
    __half* x2h   = (__half*)(scr + OFF_X2H);
    __half* hh    = (__half*)(scr + OFF_HH);
    __half* xh    = (__half*)(scr + OFF_XH);
    __half* WqkvT = (__half*)(scr + OFF_WQKVT);
    __half* WoT   = (__half*)(scr + OFF_WOT);
    __half* W1T   = (__half*)(scr + OFF_W1T);
    __half* W2T   = (__half*)(scr + OFF_W2T);
    float*  bqkv  = scr + OFF_BQKV;

    cudaFuncSetAttribute(gemm_h<0,1>, cudaFuncAttributeMaxDynamicSharedMemorySize, GT_SMEM);
    cudaFuncSetAttribute(gemm_h<1,1>, cudaFuncAttributeMaxDynamicSharedMemorySize, GT_SMEM);
    cudaFuncSetAttribute(gemm_h<2,0>, cudaFuncAttributeMaxDynamicSharedMemorySize, GT_SMEM);
    cudaFuncSetAttribute(attn_h_kernel, cudaFuncAttributeMaxDynamicSharedMemorySize, AT_SMEM);

    // merged prep (transposes + f2h + bias concat)
    prep_all<<<16396, 256>>>(x, Wq, Wk, Wv, Wo, W1, W2, bq, bk, bv,
                             xh, WqkvT, WoT, W1T, W2T, bqkv);

    // fused QKV projection -> fp16
    gemm_h<0,1><<<dim3(QKVD / BN, MTOK / BM), 256, GT_SMEM>>>(
        xh, WqkvT, bqkv, nullptr, qkvh, MTOK, QKVD, DDIM);

    // attention (fp16 tensor cores, P in registers, no scaling)
    attn_h_kernel<<<dim3(SEQ / 128, NHEAD, BATCH), 256, AT_SMEM>>>(qkvh, atth);

    // output projection + residual
    gemm_h<2,0><<<dim3(DDIM / BN, MTOK / BM), 256, GT_SMEM>>>(
        atth, WoT, bo, x, x1, MTOK, DDIM, DDIM);

    // LN1
    ln_kernel<<<MTOK, 256>>>(x1, g1, beta1, x2, x2h);

    // FFN
    gemm_h<1,1><<<dim3(FFDIM / BN, MTOK / BM), 256, GT_SMEM>>>(
        x2h, W1T, b1, nullptr, hh, MTOK, FFDIM, DDIM);
    gemm_h<2,0><<<dim3(DDIM / BN, MTOK / BM), 256, GT_SMEM>>>(
        hh, W2T, b2, x2, x3, MTOK, DDIM, FFDIM);

    // LN2 -> output
    ln_kernel<<<MTOK, 256>>>(x3, g2, beta2, out, nullptr);
}

// round 16
// speedup vs baseline: 1.1747x; 1.0910x over previous
#include <cuda_runtime.h>
#include <cuda_fp16.h>
#include <math.h>
#include <cstdint>

// ---------------------------------------------------------------------------
// Transformer block. All GEMMs + attention via mma.sync fp16 (fp32 accum).
// GEMM: 128x128 tile, 512 threads (32x32 warp tiles) -> 32 warps/SM.
// Attention: P in registers. M=4096, D=1024, H=16, hd=64, FF=4096.
// ---------------------------------------------------------------------------

#define MTOK 4096
#define DDIM 1024
#define QKVD 3072
#define FFDIM 4096
#define NHEAD 16
#define HDIM 64
#define SEQ 2048
#define BATCH 2

// scratch layout (units: floats)
#define OFF_QKVH  ((size_t)0)
#define OFF_X1    (OFF_QKVH + (size_t)MTOK*QKVD/2)
#define OFF_X2    (OFF_X1   + (size_t)MTOK*DDIM)
#define OFF_X3    (OFF_X2   + (size_t)MTOK*DDIM)
#define OFF_ATTH  (OFF_X3   + (size_t)MTOK*DDIM)
#define OFF_X2H   (OFF_ATTH + (size_t)MTOK*DDIM/2)
#define OFF_HH    (OFF_X2H  + (size_t)MTOK*DDIM/2)
#define OFF_XH    (OFF_HH   + (size_t)MTOK*FFDIM/2)
#define OFF_WQKVT (OFF_XH   + (size_t)MTOK*DDIM/2)
#define OFF_WOT   (OFF_WQKVT+ (size_t)QKVD*DDIM/2)
#define OFF_W1T   (OFF_WOT  + (size_t)DDIM*DDIM/2)
#define OFF_W2T   (OFF_W1T  + (size_t)DDIM*FFDIM/2)
#define OFF_BQKV  (OFF_W2T  + (size_t)FFDIM*DDIM/2)
#define SCRATCH_FLOATS (OFF_BQKV + (size_t)QKVD)

__device__ float g_scratch[SCRATCH_FLOATS];

// ---------------- PTX helpers ----------------
__device__ __forceinline__ void cp_async16(uint32_t dst, const void* src) {
    asm volatile("cp.async.cg.shared.global [%0], [%1], 16;"
                 :: "r"(dst), "l"(src) : "memory");
}
__device__ __forceinline__ void cp_commit() {
    asm volatile("cp.async.commit_group;" ::: "memory");
}
__device__ __forceinline__ void cp_wait0() {
    asm volatile("cp.async.wait_group 0;" ::: "memory");
}
__device__ __forceinline__ void cp_wait1() {
    asm volatile("cp.async.wait_group 1;" ::: "memory");
}
__device__ __forceinline__ uint32_t smem_u32(const void* p) {
    uint32_t a;
    asm("{ .reg .u64 t; cvta.to.shared.u64 t, %1; cvt.u32.u64 %0, t; }"
        : "=r"(a) : "l"(p));
    return a;
}
__device__ __forceinline__ void mma_f16(float* c, const uint32_t* a,
                                        const uint32_t* b) {
    asm volatile(
        "mma.sync.aligned.m16n8k16.row.col.f32.f16.f16.f32 "
        "{%0,%1,%2,%3}, {%4,%5,%6,%7}, {%8,%9}, {%0,%1,%2,%3};"
        : "+f"(c[0]), "+f"(c[1]), "+f"(c[2]), "+f"(c[3])
        : "r"(a[0]), "r"(a[1]), "r"(a[2]), "r"(a[3]), "r"(b[0]), "r"(b[1]));
}
__device__ __forceinline__ void ldmx4(uint32_t* r, uint32_t addr) {
    asm volatile(
        "ldmatrix.sync.aligned.m8n8.x4.shared.b16 {%0,%1,%2,%3}, [%4];"
        : "=r"(r[0]), "=r"(r[1]), "=r"(r[2]), "=r"(r[3]) : "r"(addr));
}
__device__ __forceinline__ void ldmx4_trans(uint32_t* r, uint32_t addr) {
    asm volatile(
        "ldmatrix.sync.aligned.m8n8.x4.trans.shared.b16 {%0,%1,%2,%3}, [%4];"
        : "=r"(r[0]), "=r"(r[1]), "=r"(r[2]), "=r"(r[3]) : "r"(addr));
}

// Fast exp on the FMA pipe (no MUFU).
__device__ __forceinline__ float fexp(float x) {
    float t = x * 1.4426950408889634f;
    t = fmaxf(t, -126.0f);
    const float fn = rintf(t);
    const float f = t - fn;
    float p = 1.33336500e-3f;
    p = fmaf(p, f, 9.61823766e-3f);
    p = fmaf(p, f, 5.55041087e-2f);
    p = fmaf(p, f, 2.40226507e-1f);
    p = fmaf(p, f, 6.93147182e-1f);
    p = fmaf(p, f, 1.0f);
    const int n = (int)fn;
    return p * __int_as_float((n + 127) << 23);
}

// ---------------------------------------------------------------------------
// fp16 GEMM: C = A @ Bt^T + bias (+ epilogue)
// CTA 128x128, BK=32 halfs, 512 threads (16 warps, 32x32 warp tiles),
// double-buffered cp.async, ldmatrix.x4. 72KB smem, <=63 regs -> 2 CTA/SM,
// 32 warps/SM for latency hiding.
// ---------------------------------------------------------------------------
#define BM 128
#define BN 128
#define ATILE_B (128 * 144)
#define BTILE_B (128 * 144)
#define GT_SMEM (2 * ATILE_B + 2 * BTILE_B)   // 73728

template <int EPI, int HOUT>
__global__ __launch_bounds__(512, 2)
void gemm_h(const __half* __restrict__ A, const __half* __restrict__ Bt,
            const float* __restrict__ bias, const float* __restrict__ res,
            void* __restrict__ Cout, int M, int N, int K)
{
    extern __shared__ __half smh[];
    const uint32_t As_u = smem_u32(smh);
    const uint32_t Bs_u = As_u + 2 * ATILE_B;

    const int tid  = threadIdx.x;
    const int warp = tid >> 5;
    const int lane = tid & 31;
    const int g    = lane >> 2;
    const int t4   = lane & 3;
    const int wm   = warp >> 2;     // 0..3, 32 rows each
    const int wn   = warp & 3;      // 0..3, 32 cols each

    const int m0 = blockIdx.y * BM;
    const int n0 = blockIdx.x * BN;

    // loaders: 128 rows x 32 halfs = 512 x 16B per matrix; 512 thr x 1 each
    const int lrow = tid >> 2;
    const int lc   = (tid & 3) * 8;
    const __half* Ag = A + (size_t)(m0 + lrow) * K + lc;
    const __half* Bg = Bt + (size_t)(n0 + lrow) * K + lc;
    const uint32_t Asm = As_u + (uint32_t)(lrow * 144 + lc * 2);
    const uint32_t Bsm = Bs_u + (uint32_t)(lrow * 144 + lc * 2);

    // ldmatrix per-lane offsets
    const uint32_t aLane = (uint32_t)((wm * 32 + (lane & 15)) * 144 +
                                      (lane >> 4) * 16);
    const uint32_t bLane = (uint32_t)((wn * 32 + (lane >> 4) * 8 + (lane & 7)) * 144 +
                                      ((lane >> 3) & 1) * 16);

    float acc[2][4][4];
#pragma unroll
    for (int mi = 0; mi < 2; mi++)
#pragma unroll
        for (int ni = 0; ni < 4; ni++)
#pragma unroll
            for (int r = 0; r < 4; r++) acc[mi][ni][r] = 0.0f;

    const int T = K >> 5;

    cp_async16(Asm, Ag);
    cp_async16(Bsm, Bg);
    cp_commit();

    for (int tb = 0; tb < T; tb++) {
        const int b = tb & 1;
        if (tb + 1 < T) {
            const uint32_t ao = (uint32_t)((b ^ 1) * ATILE_B);
            const uint32_t bo = (uint32_t)((b ^ 1) * BTILE_B);
            const size_t ko = (size_t)(tb + 1) * 32;
            cp_async16(Asm + ao, Ag + ko);
            cp_async16(Bsm + bo, Bg + ko);
            cp_commit();
            cp_wait1();
        } else {
            cp_wait0();
        }
        __syncthreads();

        const uint32_t aBase = As_u + (uint32_t)(b * ATILE_B) + aLane;
        const uint32_t bBase = Bs_u + (uint32_t)(b * BTILE_B) + bLane;
#pragma unroll
        for (int kk = 0; kk < 2; kk++) {
            uint32_t af[2][4], bf4[2][4];
#pragma unroll
            for (int mi = 0; mi < 2; mi++)
                ldmx4(af[mi], aBase + mi * (16 * 144) + kk * 32);
#pragma unroll
            for (int p = 0; p < 2; p++)
                ldmx4(bf4[p], bBase + p * (16 * 144) + kk * 32);
#pragma unroll
            for (int mi = 0; mi < 2; mi++)
#pragma unroll
                for (int ni = 0; ni < 4; ni++)
                    mma_f16(acc[mi][ni], af[mi], bf4[ni >> 1] + (ni & 1) * 2);
        }
        __syncthreads();
    }

    float* Cf = (float*)Cout;
    __half* Ch = (__half*)Cout;
#pragma unroll
    for (int mi = 0; mi < 2; mi++) {
        const int row0 = m0 + wm * 32 + mi * 16 + g;
#pragma unroll
        for (int ni = 0; ni < 4; ni++) {
            const int col = n0 + wn * 32 + ni * 8 + t4 * 2;
            const float b0 = bias[col], b1 = bias[col + 1];
            float v0 = acc[mi][ni][0] + b0;
            float v1 = acc[mi][ni][1] + b1;
            float v2 = acc[mi][ni][2] + b0;
            float v3 = acc[mi][ni][3] + b1;
            if (EPI == 1) {
                v0 = 0.5f * v0 * (1.0f + erff(v0 * 0.70710678118654752f));
                v1 = 0.5f * v1 * (1.0f + erff(v1 * 0.70710678118654752f));
                v2 = 0.5f * v2 * (1.0f + erff(v2 * 0.70710678118654752f));
                v3 = 0.5f * v3 * (1.0f + erff(v3 * 0.70710678118654752f));
            } else if (EPI == 2) {
                const float2 r0 = *(const float2*)(res + (size_t)row0 * N + col);
                const float2 r1 = *(const float2*)(res + (size_t)(row0 + 8) * N + col);
                v0 += r0.x; v1 += r0.y; v2 += r1.x; v3 += r1.y;
            }
            if (HOUT) {
                *(__half2*)(Ch + (size_t)row0 * N + col) = __floats2half2_rn(v0, v1);
                *(__half2*)(Ch + (size_t)(row0 + 8) * N + col) = __floats2half2_rn(v2, v3);
            } else {
                *(float2*)(Cf + (size_t)row0 * N + col) = make_float2(v0, v1);
                *(float2*)(Cf + (size_t)(row0 + 8) * N + col) = make_float2(v2, v3);
            }
        }
    }
}

// ---------------------------------------------------------------------------
// Merged prep: weight transposes + x->fp16 + bias concat in ONE kernel.
// ---------------------------------------------------------------------------
__global__ __launch_bounds__(256)
void prep_all(const float* __restrict__ x, const float* __restrict__ Wq,
              const float* __restrict__ Wk, const float* __restrict__ Wv,
              const float* __restrict__ Wo, const float* __restrict__ W1,
              const float* __restrict__ W2, const float* __restrict__ bq,
              const float* __restrict__ bk, const float* __restrict__ bv,
              __half* __restrict__ xh, __half* __restrict__ WqkvT,
              __half* __restrict__ WoT, __half* __restrict__ W1T,
              __half* __restrict__ W2T, float* __restrict__ bqkv)
{
    const int b = blockIdx.x;
    if (b >= 16384) {
        const int i = (b - 16384) * 256 + threadIdx.x;
        if (i < DDIM) bqkv[i] = bq[i];
        else if (i < 2 * DDIM) bqkv[i] = bk[i - DDIM];
        else bqkv[i] = bv[i - 2 * DDIM];
        return;
    }
    if (b >= 12288) {
        const int i = (b - 12288) * 256 + threadIdx.x;
        const float4 v = ((const float4*)x)[i];
        ((__half2*)xh)[2 * i]     = __floats2half2_rn(v.x, v.y);
        ((__half2*)xh)[2 * i + 1] = __floats2half2_rn(v.z, v.w);
        return;
    }
    const float* in;
    __half* out;
    int R, C, tile;
    if (b < 4096) {
        const int w = b >> 10;
        tile = b & 1023;
        R = 1024; C = 1024;
        in  = (w == 0) ? Wq : (w == 1) ? Wk : (w == 2) ? Wv : Wo;
        out = (w < 3) ? WqkvT + (size_t)w * 1024 * 1024 : WoT;
    } else if (b < 8192) {
        tile = b - 4096; R = 1024; C = 4096; in = W1; out = W1T;
    } else {
        tile = b - 8192; R = 4096; C = 1024; in = W2; out = W2T;
    }
    const int tcx = C >> 5;
    const int c0 = (tile % tcx) * 32, r0 = (tile / tcx) * 32;

    __shared__ float t[32][33];
    const int tx = threadIdx.x & 31, ty = threadIdx.x >> 5;
#pragma unroll
    for (int i = ty; i < 32; i += 8)
        t[i][tx] = in[(size_t)(r0 + i) * C + c0 + tx];
    __syncthreads();
#pragma unroll
    for (int i = ty; i < 32; i += 8)
        out[(size_t)(c0 + i) * R + r0 + tx] = __float2half_rn(t[tx][i]);
}

// ---------------------------------------------------------------------------
// fp16 tensor-core flash attention (no scaling). P stays in registers.
// ---------------------------------------------------------------------------
#define NKB (SEQ / 128)
#define AT_K_BYTES (2 * 128 * 144)
#define AT_SMEM (2 * AT_K_BYTES)   // 73728

__global__ __launch_bounds__(256, 2)
void attn_h_kernel(const __half* __restrict__ QKV, __half* __restrict__ O)
{
    extern __shared__ char smc[];
    const uint32_t sK_u = smem_u32(smc);
    const uint32_t sV_u = sK_u + AT_K_BYTES;
    __half* sQstage = (__half*)smc;

    const int bz   = blockIdx.z;
    const int h    = blockIdx.y;
    const int q0   = blockIdx.x * 128;
    const int tid  = threadIdx.x;
    const int warp = tid >> 5;
    const int lane = tid & 31;
    const int g    = lane >> 2;
    const int t4   = lane & 3;

    const size_t base = (size_t)bz * SEQ;
    const __half* Qg = QKV + (base + q0) * QKVD + h * HDIM;
    const __half* Kg = QKV + base * QKVD + DDIM + h * HDIM;
    const __half* Vg = QKV + base * QKVD + 2 * DDIM + h * HDIM;

    for (int i = tid; i < 128 * 8; i += 256) {
        const int r = i >> 3, c = (i & 7) * 8;
        *(uint4*)(sQstage + r * 72 + c) = *(const uint4*)(Qg + (size_t)r * QKVD + c);
    }
    __syncthreads();

    uint32_t qf[4][4];
    {
        const uint32_t* qrow = (const uint32_t*)sQstage + (warp * 16 + g) * 36;
#pragma unroll
        for (int ks = 0; ks < 4; ks++) {
            qf[ks][0] = qrow[ks * 8 + t4];
            qf[ks][1] = qrow[8 * 36 + ks * 8 + t4];
            qf[ks][2] = qrow[ks * 8 + t4 + 4];
            qf[ks][3] = qrow[8 * 36 + ks * 8 + t4 + 4];
        }
    }
    __syncthreads();

    float oacc[8][4];
#pragma unroll
    for (int n = 0; n < 8; n++)
#pragma unroll
        for (int r = 0; r < 4; r++) oacc[n][r] = 0.0f;
    float m0 = -1e30f, m1 = -1e30f, l0 = 0.0f, l1 = 0.0f;

    const uint32_t kLane = (uint32_t)(((lane >> 4) * 8 + (lane & 7)) * 144 +
                                      ((lane >> 3) & 1) * 16);
    const int lmat = lane >> 3;
    const int lrow = lane & 7;
    const uint32_t vLane = (uint32_t)(((lmat & 1) * 8 + lrow) * 144 +
                                      ((lmat >> 1) * 8) * 2);

#pragma unroll
    for (int i = 0; i < 4; i++) {
        const int idx = tid + i * 256;
        const int r = idx >> 3, c = (idx & 7) * 8;
        cp_async16(sK_u + (uint32_t)(r * 144 + c * 2), Kg + (size_t)r * QKVD + c);
        cp_async16(sV_u + (uint32_t)(r * 144 + c * 2), Vg + (size_t)r * QKVD + c);
    }
    cp_commit();

    for (int kb = 0; kb < NKB; kb++) {
        const int buf = kb & 1;

        if (kb + 1 < NKB) {
            const __half* Kt = Kg + (size_t)(kb + 1) * 128 * QKVD;
            const __half* Vt = Vg + (size_t)(kb + 1) * 128 * QKVD;
            const uint32_t so = (uint32_t)((buf ^ 1) * 128 * 144);
#pragma unroll
            for (int i = 0; i < 4; i++) {
                const int idx = tid + i * 256;
                const int r = idx >> 3, c = (idx & 7) * 8;
                cp_async16(sK_u + so + (uint32_t)(r * 144 + c * 2),
                           Kt + (size_t)r * QKVD + c);
                cp_async16(sV_u + so + (uint32_t)(r * 144 + c * 2),
                           Vt + (size_t)r * QKVD + c);
            }
            cp_commit();
            cp_wait1();
        } else {
            cp_wait0();
        }
        __syncthreads();

        float sc[16][4];
#pragma unroll
        for (int nt = 0; nt < 16; nt++) {
#pragma unroll
            for (int r = 0; r < 4; r++) sc[nt][r] = 0.0f;
        }
        const uint32_t kBase = sK_u + (uint32_t)(buf * 128 * 144) + kLane;
#pragma unroll
        for (int p = 0; p < 8; p++) {
            const uint32_t kp = kBase + (uint32_t)(p * 16 * 144);
#pragma unroll
            for (int ks = 0; ks < 4; ks++) {
                uint32_t kf[4];
                ldmx4(kf, kp + ks * 32);
                mma_f16(sc[2 * p],     qf[ks], kf);
                mma_f16(sc[2 * p + 1], qf[ks], kf + 2);
            }
        }

        float mx0 = m0, mx1 = m1;
#pragma unroll
        for (int nt = 0; nt < 16; nt++) {
            mx0 = fmaxf(mx0, fmaxf(sc[nt][0], sc[nt][1]));
            mx1 = fmaxf(mx1, fmaxf(sc[nt][2], sc[nt][3]));
        }
        mx0 = fmaxf(mx0, __shfl_xor_sync(0xffffffffu, mx0, 1));
        mx0 = fmaxf(mx0, __shfl_xor_sync(0xffffffffu, mx0, 2));
        mx1 = fmaxf(mx1, __shfl_xor_sync(0xffffffffu, mx1, 1));
        mx1 = fmaxf(mx1, __shfl_xor_sync(0xffffffffu, mx1, 2));

        const float s0 = fexp(m0 - mx0);
        const float s1 = fexp(m1 - mx1);
        m0 = mx0; m1 = mx1;
        l0 *= s0;  l1 *= s1;
#pragma unroll
        for (int n = 0; n < 8; n++) {
            oacc[n][0] *= s0; oacc[n][1] *= s0;
            oacc[n][2] *= s1; oacc[n][3] *= s1;
        }

        const uint32_t vBase = sV_u + (uint32_t)(buf * 128 * 144) + vLane;
        float ls0 = 0.0f, ls1 = 0.0f;
#pragma unroll
        for (int ks = 0; ks < 8; ks++) {
            uint32_t af[4];
            {
                const float p0 = fexp(sc[2 * ks][0] - mx0);
                const float p1 = fexp(sc[2 * ks][1] - mx0);
                const float p2 = fexp(sc[2 * ks][2] - mx1);
                const float p3 = fexp(sc[2 * ks][3] - mx1);
                ls0 += p0 + p1; ls1 += p2 + p3;
                const __half2 h01 = __floats2half2_rn(p0, p1);
                const __half2 h23 = __floats2half2_rn(p2, p3);
                af[0] = *(const uint32_t*)&h01;
                af[1] = *(const uint32_t*)&h23;
                const float q0f = fexp(sc[2 * ks + 1][0] - mx0);
                const float q1f = fexp(sc[2 * ks + 1][1] - mx0);
                const float q2f = fexp(sc[2 * ks + 1][2] - mx1);
                const float q3f = fexp(sc[2 * ks + 1][3] - mx1);
                ls0 += q0f + q1f; ls1 += q2f + q3f;
                const __half2 g01 = __floats2half2_rn(q0f, q1f);
                const __half2 g23 = __floats2half2_rn(q2f, q3f);
                af[2] = *(const uint32_t*)&g01;
                af[3] = *(const uint32_t*)&g23;
            }
            const uint32_t vks = vBase + (uint32_t)(ks * 16 * 144);
#pragma unroll
            for (int nt2 = 0; nt2 < 4; nt2++) {
                uint32_t vr[4];
                ldmx4_trans(vr, vks + (uint32_t)(nt2 * 32));
                mma_f16(oacc[nt2 * 2],     af, vr);
                mma_f16(oacc[nt2 * 2 + 1], af, vr + 2);
            }
        }
        l0 += ls0; l1 += ls1;
        __syncthreads();
    }

    l0 += __shfl_xor_sync(0xffffffffu, l0, 1);
    l0 += __shfl_xor_sync(0xffffffffu, l0, 2);
    l1 += __shfl_xor_sync(0xffffffffu, l1, 1);
    l1 += __shfl_xor_sync(0xffffffffu, l1, 2);
    const float inv0 = 1.0f / l0;
    const float inv1 = 1.0f / l1;

    const size_t row = base + q0 + warp * 16 + g;
    __half* Og = O + row * DDIM + h * HDIM;
#pragma unroll
    for (int nt = 0; nt < 8; nt++) {
        const int col = nt * 8 + 2 * t4;
        *(__half2*)(Og + col) =
            __floats2half2_rn(oacc[nt][0] * inv0, oacc[nt][1] * inv0);
        *(__half2*)(Og + 8 * DDIM + col) =
            __floats2half2_rn(oacc[nt][2] * inv1, oacc[nt][3] * inv1);
    }
}

// ---------------------------------------------------------------------------
// LayerNorm (D=1024), one block per row, 256 threads, float4 I/O.
// ---------------------------------------------------------------------------
__global__ __launch_bounds__(256)
void ln_kernel(const float* __restrict__ x, const float* __restrict__ g,
               const float* __restrict__ b, float* __restrict__ y,
               __half* __restrict__ yh)
{
    const int D = DDIM;
    const int row = blockIdx.x;
    const float4 v = ((const float4*)(x + (size_t)row * D))[threadIdx.x];

    float s  = v.x + v.y + v.z + v.w;
    float s2 = fmaf(v.x, v.x, fmaf(v.y, v.y, fmaf(v.z, v.z, v.w * v.w)));
#pragma unroll
    for (int o = 16; o > 0; o >>= 1) {
        s  += __shfl_xor_sync(0xffffffffu, s, o);
        s2 += __shfl_xor_sync(0xffffffffu, s2, o);
    }
    __shared__ float ss[8], ss2[8];
    const int w = threadIdx.x >> 5;
    if ((threadIdx.x & 31) == 0) { ss[w] = s; ss2[w] = s2; }
    __syncthreads();
    if (threadIdx.x < 32) {
        s  = (threadIdx.x < 8) ? ss[threadIdx.x]  : 0.f;
        s2 = (threadIdx.x < 8) ? ss2[threadIdx.x] : 0.f;
#pragma unroll
        for (int o = 4; o > 0; o >>= 1) {
            s  += __shfl_xor_sync(0xffffffffu, s, o);
            s2 += __shfl_xor_sync(0xffffffffu, s2, o);
        }
        if (threadIdx.x == 0) { ss[0] = s; ss2[0] = s2; }
    }
    __syncthreads();
    const float mu  = ss[0] * (1.0f / D);
    const float var = ss2[0] * (1.0f / D) - mu * mu;
    const float inv = rsqrtf(var + 1e-5f);

    const float4 gv = ((const float4*)g)[threadIdx.x];
    const float4 bv = ((const float4*)b)[threadIdx.x];
    float4 o4;
    o4.x = (v.x - mu) * inv * gv.x + bv.x;
    o4.y = (v.y - mu) * inv * gv.y + bv.y;
    o4.z = (v.z - mu) * inv * gv.z + bv.z;
    o4.w = (v.w - mu) * inv * gv.w + bv.w;
    ((float4*)(y + (size_t)row * D))[threadIdx.x] = o4;
    if (yh) {
        uint2 hpair;
        __half2 h0 = __floats2half2_rn(o4.x, o4.y);
        __half2 h1 = __floats2half2_rn(o4.z, o4.w);
        hpair.x = *(const uint32_t*)&h0;
        hpair.y = *(const uint32_t*)&h1;
        ((uint2*)(yh + (size_t)row * D))[threadIdx.x] = hpair;
    }
}

// ---------------------------------------------------------------------------
// Launch
// ---------------------------------------------------------------------------
extern "C" void kernel_launch(void* const* d_in, const int* in_sizes, int n_in,
                              void* d_out, int out_size)
{
    (void)in_sizes; (void)n_in; (void)out_size;
    const float* x     = (const float*)d_in[0];
    const float* Wq    = (const float*)d_in[1];
    const float* bq    = (const float*)d_in[2];
    const float* Wk    = (const float*)d_in[3];
    const float* bk    = (const float*)d_in[4];
    const float* Wv    = (const float*)d_in[5];
    const float* bv    = (const float*)d_in[6];
    const float* Wo    = (const float*)d_in[7];
    const float* bo    = (const float*)d_in[8];
    const float* W1    = (const float*)d_in[9];
    const float* b1    = (const float*)d_in[10];
    const float* W2    = (const float*)d_in[11];
    const float* b2    = (const float*)d_in[12];
    const float* g1    = (const float*)d_in[13];
    const float* beta1 = (const float*)d_in[14];
    const float* g2    = (const float*)d_in[15];
    const float* beta2 = (const float*)d_in[16];
    float* out = (float*)d_out;

    float* scr = nullptr;
    cudaGetSymbolAddress((void**)&scr, g_scratch);
    __half* qkvh  = (__half*)(scr + OFF_QKVH);
    float*  x1    = scr + OFF_X1;
    float*  x2    = scr + OFF_X2;
    float*  x3    = scr + OFF_X3;
    __half* atth  = (__half*)(scr + OFF_ATTH);
    __half* x2h   = (__half*)(scr + OFF_X2H);
    __half* hh    = (__half*)(scr + OFF_HH);
    __half* xh    = (__half*)(scr + OFF_XH);
    __half* WqkvT = (__half*)(scr + OFF_WQKVT);
    __half* WoT   = (__half*)(scr + OFF_WOT);
    __half* W1T   = (__half*)(scr + OFF_W1T);
    __half* W2T   = (__half*)(scr + OFF_W2T);
    float*  bqkv  = scr + OFF_BQKV;

    cudaFuncSetAttribute(gemm_h<0,1>, cudaFuncAttributeMaxDynamicSharedMemorySize, GT_SMEM);
    cudaFuncSetAttribute(gemm_h<1,1>, cudaFuncAttributeMaxDynamicSharedMemorySize, GT_SMEM);
    cudaFuncSetAttribute(gemm_h<2,0>, cudaFuncAttributeMaxDynamicSharedMemorySize, GT_SMEM);
    cudaFuncSetAttribute(attn_h_kernel, cudaFuncAttributeMaxDynamicSharedMemorySize, AT_SMEM);

    // merged prep (transposes + f2h + bias concat)
    prep_all<<<16396, 256>>>(x, Wq, Wk, Wv, Wo, W1, W2, bq, bk, bv,
                             xh, WqkvT, WoT, W1T, W2T, bqkv);

    // fused QKV projection -> fp16
    gemm_h<0,1><<<dim3(QKVD / BN, MTOK / BM), 512, GT_SMEM>>>(
        xh, WqkvT, bqkv, nullptr, qkvh, MTOK, QKVD, DDIM);

    // attention (fp16 tensor cores, P in registers, no scaling)
    attn_h_kernel<<<dim3(SEQ / 128, NHEAD, BATCH), 256, AT_SMEM>>>(qkvh, atth);

    // output projection + residual
    gemm_h<2,0><<<dim3(DDIM / BN, MTOK / BM), 512, GT_SMEM>>>(
        atth, WoT, bo, x, x1, MTOK, DDIM, DDIM);

    // LN1
    ln_kernel<<<MTOK, 256>>>(x1, g1, beta1, x2, x2h);

    // FFN
    gemm_h<1,1><<<dim3(FFDIM / BN, MTOK / BM), 512, GT_SMEM>>>(
        x2h, W1T, b1, nullptr, hh, MTOK, FFDIM, DDIM);
    gemm_h<2,0><<<dim3(DDIM / BN, MTOK / BM), 512, GT_SMEM>>>(
        hh, W2T, b2, x2, x3, MTOK, DDIM, FFDIM);

    // LN2 -> output
    ln_kernel<<<MTOK, 256>>>(x3, g2, beta2, out, nullptr);
}

// round 17
// speedup vs baseline: 1.1785x; 1.0032x over previous
#include <cuda_runtime.h>
#include <cuda_fp16.h>
#include <math.h>
#include <cstdint>

// ---------------------------------------------------------------------------
// Transformer block. All GEMMs + attention via mma.sync fp16 (fp32 accum).
// GEMM: 128x128 tile, 512 threads (32x32 warp tiles), 32 warps/SM.
// Attention: 256 q-rows per CTA (512 threads), P in registers.
// M=4096, D=1024, H=16, hd=64, FF=4096.
// ---------------------------------------------------------------------------

#define MTOK 4096
#define DDIM 1024
#define QKVD 3072
#define FFDIM 4096
#define NHEAD 16
#define HDIM 64
#define SEQ 2048
#define BATCH 2

// scratch layout (units: floats)
#define OFF_QKVH  ((size_t)0)
#define OFF_X1    (OFF_QKVH + (size_t)MTOK*QKVD/2)
#define OFF_X2    (OFF_X1   + (size_t)MTOK*DDIM)
#define OFF_X3    (OFF_X2   + (size_t)MTOK*DDIM)
#define OFF_ATTH  (OFF_X3   + (size_t)MTOK*DDIM)
#define OFF_X2H   (OFF_ATTH + (size_t)MTOK*DDIM/2)
#define OFF_HH    (OFF_X2H  + (size_t)MTOK*DDIM/2)
#define OFF_XH    (OFF_HH   + (size_t)MTOK*FFDIM/2)
#define OFF_WQKVT (OFF_XH   + (size_t)MTOK*DDIM/2)
#define OFF_WOT   (OFF_WQKVT+ (size_t)QKVD*DDIM/2)
#define OFF_W1T   (OFF_WOT  + (size_t)DDIM*DDIM/2)
#define OFF_W2T   (OFF_W1T  + (size_t)DDIM*FFDIM/2)
#define OFF_BQKV  (OFF_W2T  + (size_t)FFDIM*DDIM/2)
#define SCRATCH_FLOATS (OFF_BQKV + (size_t)QKVD)

__device__ float g_scratch[SCRATCH_FLOATS];

// ---------------- PTX helpers ----------------
__device__ __forceinline__ void cp_async16(uint32_t dst, const void* src) {
    asm volatile("cp.async.cg.shared.global [%0], [%1], 16;"
                 :: "r"(dst), "l"(src) : "memory");
}
__device__ __forceinline__ void cp_commit() {
    asm volatile("cp.async.commit_group;" ::: "memory");
}
__device__ __forceinline__ void cp_wait0() {
    asm volatile("cp.async.wait_group 0;" ::: "memory");
}
__device__ __forceinline__ void cp_wait1() {
    asm volatile("cp.async.wait_group 1;" ::: "memory");
}
__device__ __forceinline__ uint32_t smem_u32(const void* p) {
    uint32_t a;
    asm("{ .reg .u64 t; cvta.to.shared.u64 t, %1; cvt.u32.u64 %0, t; }"
        : "=r"(a) : "l"(p));
    return a;
}
__device__ __forceinline__ void mma_f16(float* c, const uint32_t* a,
                                        const uint32_t* b) {
    asm volatile(
        "mma.sync.aligned.m16n8k16.row.col.f32.f16.f16.f32 "
        "{%0,%1,%2,%3}, {%4,%5,%6,%7}, {%8,%9}, {%0,%1,%2,%3};"
        : "+f"(c[0]), "+f"(c[1]), "+f"(c[2]), "+f"(c[3])
        : "r"(a[0]), "r"(a[1]), "r"(a[2]), "r"(a[3]), "r"(b[0]), "r"(b[1]));
}
__device__ __forceinline__ void ldmx4(uint32_t* r, uint32_t addr) {
    asm volatile(
        "ldmatrix.sync.aligned.m8n8.x4.shared.b16 {%0,%1,%2,%3}, [%4];"
        : "=r"(r[0]), "=r"(r[1]), "=r"(r[2]), "=r"(r[3]) : "r"(addr));
}
__device__ __forceinline__ void ldmx4_trans(uint32_t* r, uint32_t addr) {
    asm volatile(
        "ldmatrix.sync.aligned.m8n8.x4.trans.shared.b16 {%0,%1,%2,%3}, [%4];"
        : "=r"(r[0]), "=r"(r[1]), "=r"(r[2]), "=r"(r[3]) : "r"(addr));
}

// Fast exp on the FMA pipe (no MUFU).
__device__ __forceinline__ float fexp(float x) {
    float t = x * 1.4426950408889634f;
    t = fmaxf(t, -126.0f);
    const float fn = rintf(t);
    const float f = t - fn;
    float p = 1.33336500e-3f;
    p = fmaf(p, f, 9.61823766e-3f);
    p = fmaf(p, f, 5.55041087e-2f);
    p = fmaf(p, f, 2.40226507e-1f);
    p = fmaf(p, f, 6.93147182e-1f);
    p = fmaf(p, f, 1.0f);
    const int n = (int)fn;
    return p * __int_as_float((n + 127) << 23);
}

// ---------------------------------------------------------------------------
// fp16 GEMM (R16 config): C = A @ Bt^T + bias (+ epilogue)
// CTA 128x128, BK=32 halfs, 512 threads (32x32 warp tiles), double-buffered
// cp.async, ldmatrix.x4. 72KB smem, 64 regs -> 2 CTA/SM = 32 warps/SM.
// ---------------------------------------------------------------------------
#define BM 128
#define BN 128
#define ATILE_B (128 * 144)
#define BTILE_B (128 * 144)
#define GT_SMEM (2 * ATILE_B + 2 * BTILE_B)   // 73728

template <int EPI, int HOUT>
__global__ __launch_bounds__(512, 2)
void gemm_h(const __half* __restrict__ A, const __half* __restrict__ Bt,
            const float* __restrict__ bias, const float* __restrict__ res,
            void* __restrict__ Cout, int M, int N, int K)
{
    extern __shared__ __half smh[];
    const uint32_t As_u = smem_u32(smh);
    const uint32_t Bs_u = As_u + 2 * ATILE_B;

    const int tid  = threadIdx.x;
    const int warp = tid >> 5;
    const int lane = tid & 31;
    const int g    = lane >> 2;
    const int t4   = lane & 3;
    const int wm   = warp >> 2;
    const int wn   = warp & 3;

    const int m0 = blockIdx.y * BM;
    const int n0 = blockIdx.x * BN;

    const int lrow = tid >> 2;
    const int lc   = (tid & 3) * 8;
    const __half* Ag = A + (size_t)(m0 + lrow) * K + lc;
    const __half* Bg = Bt + (size_t)(n0 + lrow) * K + lc;
    const uint32_t Asm = As_u + (uint32_t)(lrow * 144 + lc * 2);
    const uint32_t Bsm = Bs_u + (uint32_t)(lrow * 144 + lc * 2);

    const uint32_t aLane = (uint32_t)((wm * 32 + (lane & 15)) * 144 +
                                      (lane >> 4) * 16);
    const uint32_t bLane = (uint32_t)((wn * 32 + (lane >> 4) * 8 + (lane & 7)) * 144 +
                                      ((lane >> 3) & 1) * 16);

    float acc[2][4][4];
#pragma unroll
    for (int mi = 0; mi < 2; mi++)
#pragma unroll
        for (int ni = 0; ni < 4; ni++)
#pragma unroll
            for (int r = 0; r < 4; r++) acc[mi][ni][r] = 0.0f;

    const int T = K >> 5;

    cp_async16(Asm, Ag);
    cp_async16(Bsm, Bg);
    cp_commit();

    for (int tb = 0; tb < T; tb++) {
        const int b = tb & 1;
        if (tb + 1 < T) {
            const uint32_t ao = (uint32_t)((b ^ 1) * ATILE_B);
            const uint32_t bo = (uint32_t)((b ^ 1) * BTILE_B);
            const size_t ko = (size_t)(tb + 1) * 32;
            cp_async16(Asm + ao, Ag + ko);
            cp_async16(Bsm + bo, Bg + ko);
            cp_commit();
            cp_wait1();
        } else {
            cp_wait0();
        }
        __syncthreads();

        const uint32_t aBase = As_u + (uint32_t)(b * ATILE_B) + aLane;
        const uint32_t bBase = Bs_u + (uint32_t)(b * BTILE_B) + bLane;
#pragma unroll
        for (int kk = 0; kk < 2; kk++) {
            uint32_t af[2][4], bf4[2][4];
#pragma unroll
            for (int mi = 0; mi < 2; mi++)
                ldmx4(af[mi], aBase + mi * (16 * 144) + kk * 32);
#pragma unroll
            for (int p = 0; p < 2; p++)
                ldmx4(bf4[p], bBase + p * (16 * 144) + kk * 32);
#pragma unroll
            for (int mi = 0; mi < 2; mi++)
#pragma unroll
                for (int ni = 0; ni < 4; ni++)
                    mma_f16(acc[mi][ni], af[mi], bf4[ni >> 1] + (ni & 1) * 2);
        }
        __syncthreads();
    }

    float* Cf = (float*)Cout;
    __half* Ch = (__half*)Cout;
#pragma unroll
    for (int mi = 0; mi < 2; mi++) {
        const int row0 = m0 + wm * 32 + mi * 16 + g;
#pragma unroll
        for (int ni = 0; ni < 4; ni++) {
            const int col = n0 + wn * 32 + ni * 8 + t4 * 2;
            const float b0 = bias[col], b1 = bias[col + 1];
            float v0 = acc[mi][ni][0] + b0;
            float v1 = acc[mi][ni][1] + b1;
            float v2 = acc[mi][ni][2] + b0;
            float v3 = acc[mi][ni][3] + b1;
            if (EPI == 1) {
                v0 = 0.5f * v0 * (1.0f + erff(v0 * 0.70710678118654752f));
                v1 = 0.5f * v1 * (1.0f + erff(v1 * 0.70710678118654752f));
                v2 = 0.5f * v2 * (1.0f + erff(v2 * 0.70710678118654752f));
                v3 = 0.5f * v3 * (1.0f + erff(v3 * 0.70710678118654752f));
            } else if (EPI == 2) {
                const float2 r0 = *(const float2*)(res + (size_t)row0 * N + col);
                const float2 r1 = *(const float2*)(res + (size_t)(row0 + 8) * N + col);
                v0 += r0.x; v1 += r0.y; v2 += r1.x; v3 += r1.y;
            }
            if (HOUT) {
                *(__half2*)(Ch + (size_t)row0 * N + col) = __floats2half2_rn(v0, v1);
                *(__half2*)(Ch + (size_t)(row0 + 8) * N + col) = __floats2half2_rn(v2, v3);
            } else {
                *(float2*)(Cf + (size_t)row0 * N + col) = make_float2(v0, v1);
                *(float2*)(Cf + (size_t)(row0 + 8) * N + col) = make_float2(v2, v3);
            }
        }
    }
}

// ---------------------------------------------------------------------------
// Merged prep: weight transposes + x->fp16 + bias concat in ONE kernel.
// ---------------------------------------------------------------------------
__global__ __launch_bounds__(256)
void prep_all(const float* __restrict__ x, const float* __restrict__ Wq,
              const float* __restrict__ Wk, const float* __restrict__ Wv,
              const float* __restrict__ Wo, const float* __restrict__ W1,
              const float* __restrict__ W2, const float* __restrict__ bq,
              const float* __restrict__ bk, const float* __restrict__ bv,
              __half* __restrict__ xh, __half* __restrict__ WqkvT,
              __half* __restrict__ WoT, __half* __restrict__ W1T,
              __half* __restrict__ W2T, float* __restrict__ bqkv)
{
    const int b = blockIdx.x;
    if (b >= 16384) {
        const int i = (b - 16384) * 256 + threadIdx.x;
        if (i < DDIM) bqkv[i] = bq[i];
        else if (i < 2 * DDIM) bqkv[i] = bk[i - DDIM];
        else bqkv[i] = bv[i - 2 * DDIM];
        return;
    }
    if (b >= 12288) {
        const int i = (b - 12288) * 256 + threadIdx.x;
        const float4 v = ((const float4*)x)[i];
        ((__half2*)xh)[2 * i]     = __floats2half2_rn(v.x, v.y);
        ((__half2*)xh)[2 * i + 1] = __floats2half2_rn(v.z, v.w);
        return;
    }
    const float* in;
    __half* out;
    int R, C, tile;
    if (b < 4096) {
        const int w = b >> 10;
        tile = b & 1023;
        R = 1024; C = 1024;
        in  = (w == 0) ? Wq : (w == 1) ? Wk : (w == 2) ? Wv : Wo;
        out = (w < 3) ? WqkvT + (size_t)w * 1024 * 1024 : WoT;
    } else if (b < 8192) {
        tile = b - 4096; R = 1024; C = 4096; in = W1; out = W1T;
    } else {
        tile = b - 8192; R = 4096; C = 1024; in = W2; out = W2T;
    }
    const int tcx = C >> 5;
    const int c0 = (tile % tcx) * 32, r0 = (tile / tcx) * 32;

    __shared__ float t[32][33];
    const int tx = threadIdx.x & 31, ty = threadIdx.x >> 5;
#pragma unroll
    for (int i = ty; i < 32; i += 8)
        t[i][tx] = in[(size_t)(r0 + i) * C + c0 + tx];
    __syncthreads();
#pragma unroll
    for (int i = ty; i < 32; i += 8)
        out[(size_t)(c0 + i) * R + r0 + tx] = __float2half_rn(t[tx][i]);
}

// ---------------------------------------------------------------------------
// fp16 tensor-core flash attention (no scaling). 256 q-rows per CTA,
// 512 threads (16 warps x 16 rows), P in registers. K/V read once per
// 256 q-rows (halved traffic vs 128-row CTAs).
// ---------------------------------------------------------------------------
#define NKB (SEQ / 128)
#define AT_K_BYTES (2 * 128 * 144)
#define AT_SMEM (2 * AT_K_BYTES)   // 73728

__global__ __launch_bounds__(512, 1)
void attn_h_kernel(const __half* __restrict__ QKV, __half* __restrict__ O)
{
    extern __shared__ char smc[];
    const uint32_t sK_u = smem_u32(smc);
    const uint32_t sV_u = sK_u + AT_K_BYTES;
    __half* sQstage = (__half*)smc;      // Q staged in sK region, stride 72h

    const int bz   = blockIdx.z;
    const int h    = blockIdx.y;
    const int q0   = blockIdx.x * 256;
    const int tid  = threadIdx.x;
    const int warp = tid >> 5;           // 0..15, 16 q rows each
    const int lane = tid & 31;
    const int g    = lane >> 2;
    const int t4   = lane & 3;

    const size_t base = (size_t)bz * SEQ;
    const __half* Qg = QKV + (base + q0) * QKVD + h * HDIM;
    const __half* Kg = QKV + base * QKVD + DDIM + h * HDIM;
    const __half* Vg = QKV + base * QKVD + 2 * DDIM + h * HDIM;

    // stage Q tile [256][64]h into sK region (stride 72 halfs; 36864 B fits)
    for (int i = tid; i < 256 * 8; i += 512) {
        const int r = i >> 3, c = (i & 7) * 8;
        *(uint4*)(sQstage + r * 72 + c) = *(const uint4*)(Qg + (size_t)r * QKVD + c);
    }
    __syncthreads();

    uint32_t qf[4][4];
    {
        const uint32_t* qrow = (const uint32_t*)sQstage + (warp * 16 + g) * 36;
#pragma unroll
        for (int ks = 0; ks < 4; ks++) {
            qf[ks][0] = qrow[ks * 8 + t4];
            qf[ks][1] = qrow[8 * 36 + ks * 8 + t4];
            qf[ks][2] = qrow[ks * 8 + t4 + 4];
            qf[ks][3] = qrow[8 * 36 + ks * 8 + t4 + 4];
        }
    }
    __syncthreads();   // all warps extracted; sK region free for K tiles

    float oacc[8][4];
#pragma unroll
    for (int n = 0; n < 8; n++)
#pragma unroll
        for (int r = 0; r < 4; r++) oacc[n][r] = 0.0f;
    float m0 = -1e30f, m1 = -1e30f, l0 = 0.0f, l1 = 0.0f;

    const uint32_t kLane = (uint32_t)(((lane >> 4) * 8 + (lane & 7)) * 144 +
                                      ((lane >> 3) & 1) * 16);
    const int lmat = lane >> 3;
    const int lrow = lane & 7;
    const uint32_t vLane = (uint32_t)(((lmat & 1) * 8 + lrow) * 144 +
                                      ((lmat >> 1) * 8) * 2);

    // prologue K/V tiles: 128 rows x 8 chunks = 1024; 512 thr x 2
#pragma unroll
    for (int i = 0; i < 2; i++) {
        const int idx = tid + i * 512;
        const int r = idx >> 3, c = (idx & 7) * 8;
        cp_async16(sK_u + (uint32_t)(r * 144 + c * 2), Kg + (size_t)r * QKVD + c);
        cp_async16(sV_u + (uint32_t)(r * 144 + c * 2), Vg + (size_t)r * QKVD + c);
    }
    cp_commit();

    for (int kb = 0; kb < NKB; kb++) {
        const int buf = kb & 1;

        if (kb + 1 < NKB) {
            const __half* Kt = Kg + (size_t)(kb + 1) * 128 * QKVD;
            const __half* Vt = Vg + (size_t)(kb + 1) * 128 * QKVD;
            const uint32_t so = (uint32_t)((buf ^ 1) * 128 * 144);
#pragma unroll
            for (int i = 0; i < 2; i++) {
                const int idx = tid + i * 512;
                const int r = idx >> 3, c = (idx & 7) * 8;
                cp_async16(sK_u + so + (uint32_t)(r * 144 + c * 2),
                           Kt + (size_t)r * QKVD + c);
                cp_async16(sV_u + so + (uint32_t)(r * 144 + c * 2),
                           Vt + (size_t)r * QKVD + c);
            }
            cp_commit();
            cp_wait1();
        } else {
            cp_wait0();
        }
        __syncthreads();

        // ---- S = Q @ K^T (16 x 128 per warp) ----
        float sc[16][4];
#pragma unroll
        for (int nt = 0; nt < 16; nt++) {
#pragma unroll
            for (int r = 0; r < 4; r++) sc[nt][r] = 0.0f;
        }
        const uint32_t kBase = sK_u + (uint32_t)(buf * 128 * 144) + kLane;
#pragma unroll
        for (int p = 0; p < 8; p++) {
            const uint32_t kp = kBase + (uint32_t)(p * 16 * 144);
#pragma unroll
            for (int ks = 0; ks < 4; ks++) {
                uint32_t kf[4];
                ldmx4(kf, kp + ks * 32);
                mma_f16(sc[2 * p],     qf[ks], kf);
                mma_f16(sc[2 * p + 1], qf[ks], kf + 2);
            }
        }

        // ---- online softmax ----
        float mx0 = m0, mx1 = m1;
#pragma unroll
        for (int nt = 0; nt < 16; nt++) {
            mx0 = fmaxf(mx0, fmaxf(sc[nt][0], sc[nt][1]));
            mx1 = fmaxf(mx1, fmaxf(sc[nt][2], sc[nt][3]));
        }
        mx0 = fmaxf(mx0, __shfl_xor_sync(0xffffffffu, mx0, 1));
        mx0 = fmaxf(mx0, __shfl_xor_sync(0xffffffffu, mx0, 2));
        mx1 = fmaxf(mx1, __shfl_xor_sync(0xffffffffu, mx1, 1));
        mx1 = fmaxf(mx1, __shfl_xor_sync(0xffffffffu, mx1, 2));

        const float s0 = fexp(m0 - mx0);
        const float s1 = fexp(m1 - mx1);
        m0 = mx0; m1 = mx1;
        l0 *= s0;  l1 *= s1;
#pragma unroll
        for (int n = 0; n < 8; n++) {
            oacc[n][0] *= s0; oacc[n][1] *= s0;
            oacc[n][2] *= s1; oacc[n][3] *= s1;
        }

        // ---- fused P conversion + P @ V (P never touches smem) ----
        const uint32_t vBase = sV_u + (uint32_t)(buf * 128 * 144) + vLane;
        float ls0 = 0.0f, ls1 = 0.0f;
#pragma unroll
        for (int ks = 0; ks < 8; ks++) {
            uint32_t af[4];
            {
                const float p0 = fexp(sc[2 * ks][0] - mx0);
                const float p1 = fexp(sc[2 * ks][1] - mx0);
                const float p2 = fexp(sc[2 * ks][2] - mx1);
                const float p3 = fexp(sc[2 * ks][3] - mx1);
                ls0 += p0 + p1; ls1 += p2 + p3;
                const __half2 h01 = __floats2half2_rn(p0, p1);
                const __half2 h23 = __floats2half2_rn(p2, p3);
                af[0] = *(const uint32_t*)&h01;
                af[1] = *(const uint32_t*)&h23;
                const float q0f = fexp(sc[2 * ks + 1][0] - mx0);
                const float q1f = fexp(sc[2 * ks + 1][1] - mx0);
                const float q2f = fexp(sc[2 * ks + 1][2] - mx1);
                const float q3f = fexp(sc[2 * ks + 1][3] - mx1);
                ls0 += q0f + q1f; ls1 += q2f + q3f;
                const __half2 g01 = __floats2half2_rn(q0f, q1f);
                const __half2 g23 = __floats2half2_rn(q2f, q3f);
                af[2] = *(const uint32_t*)&g01;
                af[3] = *(const uint32_t*)&g23;
            }
            const uint32_t vks = vBase + (uint32_t)(ks * 16 * 144);
#pragma unroll
            for (int nt2 = 0; nt2 < 4; nt2++) {
                uint32_t vr[4];
                ldmx4_trans(vr, vks + (uint32_t)(nt2 * 32));
                mma_f16(oacc[nt2 * 2],     af, vr);
                mma_f16(oacc[nt2 * 2 + 1], af, vr + 2);
            }
        }
        l0 += ls0; l1 += ls1;
        __syncthreads();
    }

    l0 += __shfl_xor_sync(0xffffffffu, l0, 1);
    l0 += __shfl_xor_sync(0xffffffffu, l0, 2);
    l1 += __shfl_xor_sync(0xffffffffu, l1, 1);
    l1 += __shfl_xor_sync(0xffffffffu, l1, 2);
    const float inv0 = 1.0f / l0;
    const float inv1 = 1.0f / l1;

    const size_t row = base + q0 + warp * 16 + g;
    __half* Og = O + row * DDIM + h * HDIM;
#pragma unroll
    for (int nt = 0; nt < 8; nt++) {
        const int col = nt * 8 + 2 * t4;
        *(__half2*)(Og + col) =
            __floats2half2_rn(oacc[nt][0] * inv0, oacc[nt][1] * inv0);
        *(__half2*)(Og + 8 * DDIM + col) =
            __floats2half2_rn(oacc[nt][2] * inv1, oacc[nt][3] * inv1);
    }
}

// ---------------------------------------------------------------------------
// LayerNorm (D=1024), one block per row, 256 threads, float4 I/O.
// ---------------------------------------------------------------------------
__global__ __launch_bounds__(256)
void ln_kernel(const float* __restrict__ x, const float* __restrict__ g,
               const float* __restrict__ b, float* __restrict__ y,
               __half* __restrict__ yh)
{
    const int D = DDIM;
    const int row = blockIdx.x;
    const float4 v = ((const float4*)(x + (size_t)row * D))[threadIdx.x];

    float s  = v.x + v.y + v.z + v.w;
    float s2 = fmaf(v.x, v.x, fmaf(v.y, v.y, fmaf(v.z, v.z, v.w * v.w)));
#pragma unroll
    for (int o = 16; o > 0; o >>= 1) {
        s  += __shfl_xor_sync(0xffffffffu, s, o);
        s2 += __shfl_xor_sync(0xffffffffu, s2, o);
    }
    __shared__ float ss[8], ss2[8];
    const int w = threadIdx.x >> 5;
    if ((threadIdx.x & 31) == 0) { ss[w] = s; ss2[w] = s2; }
    __syncthreads();
    if (threadIdx.x < 32) {
        s  = (threadIdx.x < 8) ? ss[threadIdx.x]  : 0.f;
        s2 = (threadIdx.x < 8) ? ss2[threadIdx.x] : 0.f;
#pragma unroll
        for (int o = 4; o > 0; o >>= 1) {
            s  += __shfl_xor_sync(0xffffffffu, s, o);
            s2 += __shfl_xor_sync(0xffffffffu, s2, o);
        }
        if (threadIdx.x == 0) { ss[0] = s; ss2[0] = s2; }
    }
    __syncthreads();
    const float mu  = ss[0] * (1.0f / D);
    const float var = ss2[0] * (1.0f / D) - mu * mu;
    const float inv = rsqrtf(var + 1e-5f);

    const float4 gv = ((const float4*)g)[threadIdx.x];
    const float4 bv = ((const float4*)b)[threadIdx.x];
    float4 o4;
    o4.x = (v.x - mu) * inv * gv.x + bv.x;
    o4.y = (v.y - mu) * inv * gv.y + bv.y;
    o4.z = (v.z - mu) * inv * gv.z + bv.z;
    o4.w = (v.w - mu) * inv * gv.w + bv.w;
    ((float4*)(y + (size_t)row * D))[threadIdx.x] = o4;
    if (yh) {
        uint2 hpair;
        __half2 h0 = __floats2half2_rn(o4.x, o4.y);
        __half2 h1 = __floats2half2_rn(o4.z, o4.w);
        hpair.x = *(const uint32_t*)&h0;
        hpair.y = *(const uint32_t*)&h1;
        ((uint2*)(yh + (size_t)row * D))[threadIdx.x] = hpair;
    }
}

// ---------------------------------------------------------------------------
// Launch
// ---------------------------------------------------------------------------
extern "C" void kernel_launch(void* const* d_in, const int* in_sizes, int n_in,
                              void* d_out, int out_size)
{
    (void)in_sizes; (void)n_in; (void)out_size;
    const float* x     = (const float*)d_in[0];
    const float* Wq    = (const float*)d_in[1];
    const float* bq    = (const float*)d_in[2];
    const float* Wk    = (const float*)d_in[3];
    const float* bk    = (const float*)d_in[4];
    const float* Wv    = (const float*)d_in[5];
    const float* bv    = (const float*)d_in[6];
    const float* Wo    = (const float*)d_in[7];
    const float* bo    = (const float*)d_in[8];
    const float* W1    = (const float*)d_in[9];
    const float* b1    = (const float*)d_in[10];
    const float* W2    = (const float*)d_in[11];
    const float* b2    = (const float*)d_in[12];
    const float* g1    = (const float*)d_in[13];
    const float* beta1 = (const float*)d_in[14];
    const float* g2    = (const float*)d_in[15];
    const float* beta2 = (const float*)d_in[16];
    float* out = (float*)d_out;

    float* scr = nullptr;
    cudaGetSymbolAddress((void**)&scr, g_scratch);
    __half* qkvh  = (__half*)(scr + OFF_QKVH);
    float*  x1    = scr + OFF_X1;
    float*  x2    = scr + OFF_X2;
    float*  x3    = scr + OFF_X3;
    __half* atth  = (__half*)(scr + OFF_ATTH);
    __half* x2h   = (__half*)(scr + OFF_X2H);
    __half* hh    = (__half*)(scr + OFF_HH);
    __half* xh    = (__half*)(scr + OFF_XH);
    __half* WqkvT = (__half*)(scr + OFF_WQKVT);
    __half* WoT   = (__half*)(scr + OFF_WOT);
    __half* W1T   = (__half*)(scr + OFF_W1T);
    __half* W2T   = (__half*)(scr + OFF_W2T);
    float*  bqkv  = scr + OFF_BQKV;

    cudaFuncSetAttribute(gemm_h<0,1>, cudaFuncAttributeMaxDynamicSharedMemorySize, GT_SMEM);
    cudaFuncSetAttribute(gemm_h<1,1>, cudaFuncAttributeMaxDynamicSharedMemorySize, GT_SMEM);
    cudaFuncSetAttribute(gemm_h<2,0>, cudaFuncAttributeMaxDynamicSharedMemorySize, GT_SMEM);
    cudaFuncSetAttribute(attn_h_kernel, cudaFuncAttributeMaxDynamicSharedMemorySize, AT_SMEM);

    // merged prep (transposes + f2h + bias concat)
    prep_all<<<16396, 256>>>(x, Wq, Wk, Wv, Wo, W1, W2, bq, bk, bv,
                             xh, WqkvT, WoT, W1T, W2T, bqkv);

    // fused QKV projection -> fp16
    gemm_h<0,1><<<dim3(QKVD / BN, MTOK / BM), 512, GT_SMEM>>>(
        xh, WqkvT, bqkv, nullptr, qkvh, MTOK, QKVD, DDIM);

    // attention (fp16 tensor cores, 256 q-rows/CTA, no scaling)
    attn_h_kernel<<<dim3(SEQ / 256, NHEAD, BATCH), 512, AT_SMEM>>>(qkvh, atth);

    // output projection + residual
    gemm_h<2,0><<<dim3(DDIM / BN, MTOK / BM), 512, GT_SMEM>>>(
        atth, WoT, bo, x, x1, MTOK, DDIM, DDIM);

    // LN1
    ln_kernel<<<MTOK, 256>>>(x1, g1, beta1, x2, x2h);

    // FFN
    gemm_h<1,1><<<dim3(FFDIM / BN, MTOK / BM), 512, GT_SMEM>>>(
        x2h, W1T, b1, nullptr, hh, MTOK, FFDIM, DDIM);
    gemm_h<2,0><<<dim3(DDIM / BN, MTOK / BM), 512, GT_SMEM>>>(
        hh, W2T, b2, x2, x3, MTOK, DDIM, FFDIM);

    // LN2 -> output
    ln_kernel<<<MTOK, 256>>>(x3, g2, beta2, out, nullptr);
}